// round 12
// baseline (speedup 1.0000x reference)
#include <cuda_runtime.h>
#include <cstdint>

// ---------------- problem constants ----------------
#define N_NODES 50000
#define F_IN    512
#define F_H     256
#define F_OUT   128
#define E_EDGES 800000
#define SCAN_B  1024
#define SCAN_NB ((N_NODES + SCAN_B - 1) / SCAN_B)   // 49
#define C0_ROWS 25088                                // 196 tiles of 128
#define C1_ROWS (N_NODES - C0_ROWS)                  // 24912 (195 tiles)

// ---------------- scratch (static device globals; no runtime alloc) --------
__device__ int   g_is64;
__device__ int   g_deg [N_NODES];
__device__ int   g_cursor[N_NODES];
__device__ int   g_rowstart[N_NODES + 1];
__device__ int   g_bsum[SCAN_NB];
__device__ int   g_csrc[E_EDGES];
__device__ float g_dinv[N_NODES];
__device__ unsigned g_mask[(size_t)N_NODES * F_H / 32];   // packed dropout mask
__device__ float g_h1  [(size_t)N_NODES * F_H];
__device__ uint16_t g_h1b[(size_t)N_NODES * F_H];
__device__ float g_agg1[(size_t)N_NODES * F_H];
__device__ float g_h2  [(size_t)N_NODES * F_OUT];
__device__ uint16_t g_h2b[(size_t)N_NODES * F_OUT];
__device__ uint32_t g_w1t[F_IN * F_H];
__device__ uint32_t g_w2t[F_H * F_OUT];

// ---------------- helpers ----------------
__device__ __forceinline__ uint32_t f2tf32(float f) {
    uint32_t r; asm("cvt.rna.tf32.f32 %0, %1;" : "=r"(r) : "f"(f)); return r;
}
__device__ __forceinline__ uint32_t pack_bf16x2(float lo, float hi) {
    uint32_t r; asm("cvt.rn.bf16x2.f32 %0, %1, %2;" : "=r"(r) : "f"(hi), "f"(lo)); return r;
}
__device__ __forceinline__ float bf_lo(uint32_t u) { return __uint_as_float(u << 16); }
__device__ __forceinline__ float bf_hi(uint32_t u) { return __uint_as_float(u & 0xffff0000u); }
__device__ __forceinline__ uint32_t smem_u32(const void* p) {
    uint32_t a;
    asm("{ .reg .u64 t; cvta.to.shared.u64 t, %1; cvt.u32.u64 %0, t; }" : "=r"(a) : "l"(p));
    return a;
}
__device__ __forceinline__ void cp16(uint32_t s, const void* g) {
    asm volatile("cp.async.cg.shared.global [%0], [%1], 16;" :: "r"(s), "l"(g));
}
__device__ __forceinline__ void cp_commit() {
    asm volatile("cp.async.commit_group;" ::: "memory");
}
template <int N>
__device__ __forceinline__ void cp_wait() {
    asm volatile("cp.async.wait_group %0;" :: "n"(N) : "memory");
}

// ---------------- edge index access (int32 or int64) ----------------
__device__ __forceinline__ int edge_at(const void* ei, long long i) {
    if (g_is64) return (int)((const long long*)ei)[i];
    return ((const int*)ei)[i];
}
__global__ void k_detect(const int* ei32) {
    __shared__ int any_nonzero;
    if (threadIdx.x == 0) any_nonzero = 0;
    __syncthreads();
    if (ei32[2 * threadIdx.x + 1] != 0) atomicOr(&any_nonzero, 1);
    __syncthreads();
    if (threadIdx.x == 0) g_is64 = (any_nonzero == 0) ? 1 : 0;
}

// ---------------- degree / CSR ----------------
__global__ void k_zero() {
    int i = blockIdx.x * blockDim.x + threadIdx.x;
    if (i < N_NODES) g_deg[i] = 0;
}
__global__ void k_degree(const void* ei) {
    int e = blockIdx.x * blockDim.x + threadIdx.x;
    if (e < E_EDGES) atomicAdd(&g_deg[edge_at(ei, (long long)E_EDGES + e)], 1);
}
__global__ void __launch_bounds__(SCAN_B) k_scan1() {
    __shared__ int ws[32];
    int i = blockIdx.x * SCAN_B + threadIdx.x;
    int lane = threadIdx.x & 31, warp = threadIdx.x >> 5;
    int v = (i < N_NODES) ? g_deg[i] : 0;
    if (i < N_NODES) g_dinv[i] = rsqrtf((float)(v + 1));
    int inc = v;
#pragma unroll
    for (int off = 1; off < 32; off <<= 1) {
        int y = __shfl_up_sync(0xffffffffu, inc, off);
        if (lane >= off) inc += y;
    }
    if (lane == 31) ws[warp] = inc;
    __syncthreads();
    if (warp == 0) {
        int s = ws[lane];
        int sinc = s;
#pragma unroll
        for (int off = 1; off < 32; off <<= 1) {
            int y = __shfl_up_sync(0xffffffffu, sinc, off);
            if (lane >= off) sinc += y;
        }
        ws[lane] = sinc - s;
        if (lane == 31) g_bsum[blockIdx.x] = sinc;
    }
    __syncthreads();
    if (i < N_NODES) g_rowstart[i] = ws[warp] + inc - v;
}
__global__ void k_scan2() {
    __shared__ int s[SCAN_NB];
    if (threadIdx.x < SCAN_NB) s[threadIdx.x] = g_bsum[threadIdx.x];
    __syncthreads();
    if (threadIdx.x == 0) {
        int run = 0;
        for (int b = 0; b < SCAN_NB; b++) { int t = s[b]; s[b] = run; run += t; }
    }
    __syncthreads();
    if (threadIdx.x < SCAN_NB) g_bsum[threadIdx.x] = s[threadIdx.x];
}
__global__ void k_scan3() {
    int i = blockIdx.x * blockDim.x + threadIdx.x;
    if (i < N_NODES) {
        int rs = g_rowstart[i] + g_bsum[i >> 10];
        g_rowstart[i] = rs;
        g_cursor[i]   = rs;
    }
    if (i == 0) g_rowstart[N_NODES] = E_EDGES;
}
__global__ void k_fill(const void* ei) {
    int e = blockIdx.x * blockDim.x + threadIdx.x;
    if (e >= E_EDGES) return;
    int src = edge_at(ei, e);
    int dst = edge_at(ei, (long long)E_EDGES + e);
    int pos = atomicAdd(&g_cursor[dst], 1);
    g_csrc[pos] = src;
}

// ---------------- W prep ----------------
template <int Kd, int Nd>
__global__ void k_wprep(const float* __restrict__ W, uint32_t* __restrict__ Wt) {
    int i = blockIdx.x * blockDim.x + threadIdx.x;
    if (i >= Kd * Nd) return;
    int k = i / Nd, n = i % Nd;
    Wt[(size_t)n * Kd + k] = f2tf32(W[i]);
}

// ---------------- threefry2x32 key (0,42) ----------------
__device__ __forceinline__ void threefry_0_42(unsigned c0, unsigned c1,
                                              unsigned& o0, unsigned& o1) {
    const unsigned ks0 = 0u, ks1 = 42u, ks2 = 0u ^ 42u ^ 0x1BD11BDAu;
    unsigned x0 = c0 + ks0, x1 = c1 + ks1;
#define TF_RND(r) { x0 += x1; x1 = __funnelshift_l(x1, x1, (r)); x1 ^= x0; }
    TF_RND(13) TF_RND(15) TF_RND(26) TF_RND(6)
    x0 += ks1; x1 += ks2 + 1u;
    TF_RND(17) TF_RND(29) TF_RND(16) TF_RND(24)
    x0 += ks2; x1 += ks0 + 2u;
    TF_RND(13) TF_RND(15) TF_RND(26) TF_RND(6)
    x0 += ks0; x1 += ks1 + 3u;
    TF_RND(17) TF_RND(29) TF_RND(16) TF_RND(24)
    x0 += ks1; x1 += ks2 + 4u;
    TF_RND(13) TF_RND(15) TF_RND(26) TF_RND(6)
    x0 += ks2; x1 += ks0 + 5u;
#undef TF_RND
    o0 = x0; o1 = x1;
}

// ---------------- dropout mask precompute (index-only; overlaps GEMM1) -----
__global__ void __launch_bounds__(256) k_mask() {
    unsigned i = blockIdx.x * blockDim.x + threadIdx.x;   // element index
    unsigned r0, r1;
    threefry_0_42(0u, i, r0, r1);
    unsigned bits = r0 ^ r1;
    float u = __uint_as_float((bits >> 9) | 0x3f800000u) - 1.0f;
    unsigned word = __ballot_sync(0xffffffffu, u < 0.8f);
    if ((threadIdx.x & 31) == 0) g_mask[i >> 5] = word;
}

// ---------------- tensor-core GEMM via mma.sync (tf32), cp.async x3 -------
// C[row0+.., Nd] = A * Bt^T for this grid's tiles. Also writes bf16 copy Cb.
template <int Kd, int Nd>
__global__ void __launch_bounds__(512) k_gemm_mma(const float* __restrict__ A,
                                                  const uint32_t* __restrict__ Bt,
                                                  float* __restrict__ C,
                                                  uint16_t* __restrict__ Cb,
                                                  int M, int row0) {
    constexpr int WN  = Nd / 8;
    constexpr int NT  = WN / 8;
    constexpr int STR = 36;
    constexpr int ABYTES = 128 * STR * 4;
    constexpr int BBYTES = Nd * STR * 4;
    constexpr int KT = Kd / 32;
    extern __shared__ char smem[];
    const uint32_t sb = smem_u32(smem);

    const int t    = threadIdx.x;
    const int lane = t & 31, wid = t >> 5;
    const int gid  = lane >> 2, tig = lane & 3;
    const int wm   = (wid & 1) * 64;
    const int wn   = (wid >> 1) * WN;
    const int brow = row0 + blockIdx.x * 128;

    auto load_tile = [&](int kt, int buf) {
        uint32_t sA = sb + buf * ABYTES;
        uint32_t sB = sb + 3 * ABYTES + buf * BBYTES;
#pragma unroll
        for (int it = 0; it < 2; it++) {
            int f4 = it * 512 + t;
            int row = f4 >> 3, cq = f4 & 7;
            int grow = brow + row; if (grow > M - 1) grow = M - 1;
            cp16(sA + (uint32_t)(row * STR + cq * 4) * 4,
                 A + (size_t)grow * Kd + kt * 32 + cq * 4);
        }
#pragma unroll
        for (int it = 0; it < Nd / 64; it++) {
            int f4 = it * 512 + t;
            int n = f4 >> 3, cq = f4 & 7;
            cp16(sB + (uint32_t)(n * STR + cq * 4) * 4,
                 Bt + (size_t)n * Kd + kt * 32 + cq * 4);
        }
        cp_commit();
    };

    float c[4][NT][4];
#pragma unroll
    for (int mt = 0; mt < 4; mt++)
#pragma unroll
        for (int nt = 0; nt < NT; nt++)
#pragma unroll
            for (int i = 0; i < 4; i++) c[mt][nt][i] = 0.0f;

    load_tile(0, 0);
    load_tile(1, 1);
    for (int kt = 0; kt < KT; kt++) {
        int buf = kt % 3;
        if (kt + 2 < KT) { load_tile(kt + 2, (kt + 2) % 3); cp_wait<2>(); }
        else if (kt + 1 < KT) { cp_wait<1>(); }
        else { cp_wait<0>(); }
        __syncthreads();
        const uint32_t* As = (const uint32_t*)(smem + buf * ABYTES);
        const uint32_t* Bs = (const uint32_t*)(smem + 3 * ABYTES + buf * BBYTES);
#pragma unroll
        for (int ks = 0; ks < 4; ks++) {
            uint32_t a[4][4], b[NT][2];
#pragma unroll
            for (int mt = 0; mt < 4; mt++) {
                int r = wm + mt * 16;
                a[mt][0] = As[(r + gid)     * STR + ks * 8 + tig];
                a[mt][1] = As[(r + gid + 8) * STR + ks * 8 + tig];
                a[mt][2] = As[(r + gid)     * STR + ks * 8 + tig + 4];
                a[mt][3] = As[(r + gid + 8) * STR + ks * 8 + tig + 4];
            }
#pragma unroll
            for (int nt = 0; nt < NT; nt++) {
                int n = wn + nt * 8 + gid;
                b[nt][0] = Bs[n * STR + ks * 8 + tig];
                b[nt][1] = Bs[n * STR + ks * 8 + tig + 4];
            }
#pragma unroll
            for (int mt = 0; mt < 4; mt++)
#pragma unroll
                for (int nt = 0; nt < NT; nt++)
                    asm volatile(
                        "mma.sync.aligned.m16n8k8.row.col.f32.tf32.tf32.f32 "
                        "{%0,%1,%2,%3}, {%4,%5,%6,%7}, {%8,%9}, {%0,%1,%2,%3};"
                        : "+f"(c[mt][nt][0]), "+f"(c[mt][nt][1]),
                          "+f"(c[mt][nt][2]), "+f"(c[mt][nt][3])
                        : "r"(a[mt][0]), "r"(a[mt][1]), "r"(a[mt][2]), "r"(a[mt][3]),
                          "r"(b[nt][0]), "r"(b[nt][1]));
        }
        __syncthreads();
    }

#pragma unroll
    for (int mt = 0; mt < 4; mt++)
#pragma unroll
        for (int nt = 0; nt < NT; nt++) {
            int col = wn + nt * 8 + tig * 2;
            int r0  = brow + wm + mt * 16 + gid;
            int r1  = r0 + 8;
            if (r0 < M) {
                *(float2*)(C + (size_t)r0 * Nd + col) = make_float2(c[mt][nt][0], c[mt][nt][1]);
                *(uint32_t*)(Cb + (size_t)r0 * Nd + col) = pack_bf16x2(c[mt][nt][0], c[mt][nt][1]);
            }
            if (r1 < M) {
                *(float2*)(C + (size_t)r1 * Nd + col) = make_float2(c[mt][nt][2], c[mt][nt][3]);
                *(uint32_t*)(Cb + (size_t)r1 * Nd + col) = pack_bf16x2(c[mt][nt][2], c[mt][nt][3]);
            }
        }
}

// ---------------- layer1 pull-agg: agg1 = mask ∘ relu(Â h1 + b1) -----------
// 32 threads per node, 8 cols each; bf16 gathers; precomputed mask.
__global__ void __launch_bounds__(256) k_agg1(const float* __restrict__ b1,
                                              int node0, int ncount) {
    int g    = threadIdx.x >> 5;
    int lane = threadIdx.x & 31;
    int node = node0 + blockIdx.x * 8 + g;
    if (node >= node0 + ncount) return;

    float dn = g_dinv[node];
    float s = dn * dn;
    const float4* hf = (const float4*)(g_h1 + (size_t)node * F_H);
    float4 a0 = hf[lane * 2], a1 = hf[lane * 2 + 1];
    float acc[8] = {a0.x * s, a0.y * s, a0.z * s, a0.w * s,
                    a1.x * s, a1.y * s, a1.z * s, a1.w * s};

    int e0 = g_rowstart[node], e1 = g_rowstart[node + 1];
    int j = e0;
    for (; j + 2 <= e1; j += 2) {
        int s0 = g_csrc[j], s1 = g_csrc[j + 1];
        float n0 = dn * g_dinv[s0], n1 = dn * g_dinv[s1];
        uint4 r0 = ((const uint4*)(g_h1b + (size_t)s0 * F_H))[lane];
        uint4 r1 = ((const uint4*)(g_h1b + (size_t)s1 * F_H))[lane];
        acc[0] = fmaf(n0, bf_lo(r0.x), acc[0]); acc[1] = fmaf(n0, bf_hi(r0.x), acc[1]);
        acc[2] = fmaf(n0, bf_lo(r0.y), acc[2]); acc[3] = fmaf(n0, bf_hi(r0.y), acc[3]);
        acc[4] = fmaf(n0, bf_lo(r0.z), acc[4]); acc[5] = fmaf(n0, bf_hi(r0.z), acc[5]);
        acc[6] = fmaf(n0, bf_lo(r0.w), acc[6]); acc[7] = fmaf(n0, bf_hi(r0.w), acc[7]);
        acc[0] = fmaf(n1, bf_lo(r1.x), acc[0]); acc[1] = fmaf(n1, bf_hi(r1.x), acc[1]);
        acc[2] = fmaf(n1, bf_lo(r1.y), acc[2]); acc[3] = fmaf(n1, bf_hi(r1.y), acc[3]);
        acc[4] = fmaf(n1, bf_lo(r1.z), acc[4]); acc[5] = fmaf(n1, bf_hi(r1.z), acc[5]);
        acc[6] = fmaf(n1, bf_lo(r1.w), acc[6]); acc[7] = fmaf(n1, bf_hi(r1.w), acc[7]);
    }
    if (j < e1) {
        int s0 = g_csrc[j];
        float n0 = dn * g_dinv[s0];
        uint4 r0 = ((const uint4*)(g_h1b + (size_t)s0 * F_H))[lane];
        acc[0] = fmaf(n0, bf_lo(r0.x), acc[0]); acc[1] = fmaf(n0, bf_hi(r0.x), acc[1]);
        acc[2] = fmaf(n0, bf_lo(r0.y), acc[2]); acc[3] = fmaf(n0, bf_hi(r0.y), acc[3]);
        acc[4] = fmaf(n0, bf_lo(r0.z), acc[4]); acc[5] = fmaf(n0, bf_hi(r0.z), acc[5]);
        acc[6] = fmaf(n0, bf_lo(r0.w), acc[6]); acc[7] = fmaf(n0, bf_hi(r0.w), acc[7]);
    }
    const float4 bb0 = ((const float4*)b1)[lane * 2];
    const float4 bb1 = ((const float4*)b1)[lane * 2 + 1];
    float bias[8] = {bb0.x, bb0.y, bb0.z, bb0.w, bb1.x, bb1.y, bb1.z, bb1.w};
    // mask word covers 32 elements = 4 lanes; this lane's 8 bits at (lane&3)*8
    unsigned w  = g_mask[node * (F_H / 32) + (lane >> 2)];
    unsigned sh = (lane & 3) * 8;
    float outv[8];
#pragma unroll
    for (int q = 0; q < 8; q++) {
        float v = fmaxf(acc[q] + bias[q], 0.0f);
        outv[q] = ((w >> (sh + q)) & 1u) ? v * 1.25f : 0.0f;
    }
    float4* dst = (float4*)(g_agg1 + (size_t)node * F_H);
    dst[lane * 2]     = make_float4(outv[0], outv[1], outv[2], outv[3]);
    dst[lane * 2 + 1] = make_float4(outv[4], outv[5], outv[6], outv[7]);
}

// ---------------- layer2 pull-agg + bias + softmax -> d_out ----------------
__global__ void __launch_bounds__(256) k_agg2(const float* __restrict__ b2,
                                              float* __restrict__ out) {
    int g    = threadIdx.x >> 5;
    int lane = threadIdx.x & 31;
    int node = blockIdx.x * 8 + g;
    if (node >= N_NODES) return;

    float dn = g_dinv[node];
    float4 acc = ((const float4*)(g_h2 + (size_t)node * F_OUT))[lane];
    float s = dn * dn;
    acc.x *= s; acc.y *= s; acc.z *= s; acc.w *= s;

    int e0 = g_rowstart[node], e1 = g_rowstart[node + 1];
    int j = e0;
    for (; j + 2 <= e1; j += 2) {
        int s0 = g_csrc[j], s1 = g_csrc[j + 1];
        float n0 = dn * g_dinv[s0], n1 = dn * g_dinv[s1];
        uint2 r0 = ((const uint2*)(g_h2b + (size_t)s0 * F_OUT))[lane];
        uint2 r1 = ((const uint2*)(g_h2b + (size_t)s1 * F_OUT))[lane];
        acc.x = fmaf(n0, bf_lo(r0.x), acc.x); acc.y = fmaf(n0, bf_hi(r0.x), acc.y);
        acc.z = fmaf(n0, bf_lo(r0.y), acc.z); acc.w = fmaf(n0, bf_hi(r0.y), acc.w);
        acc.x = fmaf(n1, bf_lo(r1.x), acc.x); acc.y = fmaf(n1, bf_hi(r1.x), acc.y);
        acc.z = fmaf(n1, bf_lo(r1.y), acc.z); acc.w = fmaf(n1, bf_hi(r1.y), acc.w);
    }
    if (j < e1) {
        int s0 = g_csrc[j];
        float n0 = dn * g_dinv[s0];
        uint2 r0 = ((const uint2*)(g_h2b + (size_t)s0 * F_OUT))[lane];
        acc.x = fmaf(n0, bf_lo(r0.x), acc.x); acc.y = fmaf(n0, bf_hi(r0.x), acc.y);
        acc.z = fmaf(n0, bf_lo(r0.y), acc.z); acc.w = fmaf(n0, bf_hi(r0.y), acc.w);
    }
    float4 bb = ((const float4*)b2)[lane];
    acc.x += bb.x; acc.y += bb.y; acc.z += bb.z; acc.w += bb.w;

    float m = fmaxf(fmaxf(acc.x, acc.y), fmaxf(acc.z, acc.w));
#pragma unroll
    for (int off = 16; off > 0; off >>= 1)
        m = fmaxf(m, __shfl_xor_sync(0xffffffffu, m, off));
    acc.x = expf(acc.x - m); acc.y = expf(acc.y - m);
    acc.z = expf(acc.z - m); acc.w = expf(acc.w - m);
    float sum = acc.x + acc.y + acc.z + acc.w;
#pragma unroll
    for (int off = 16; off > 0; off >>= 1)
        sum += __shfl_xor_sync(0xffffffffu, sum, off);
    float inv = 1.0f / sum;
    acc.x *= inv; acc.y *= inv; acc.z *= inv; acc.w *= inv;
    ((float4*)(out + (size_t)node * F_OUT))[lane] = acc;
}

// ---------------- launcher (fork-join + chunked layer-1/2 pipeline) -------
extern "C" void kernel_launch(void* const* d_in, const int* in_sizes, int n_in,
                              void* d_out, int out_size) {
    const float* x  = (const float*)d_in[0];
    const void*  ei = d_in[1];
    const float* W1 = (const float*)d_in[2];
    const float* b1 = (const float*)d_in[3];
    const float* W2 = (const float*)d_in[4];
    const float* b2 = (const float*)d_in[5];
    float* out = (float*)d_out;

    float* h1;   cudaGetSymbolAddress((void**)&h1,   g_h1);
    float* agg1; cudaGetSymbolAddress((void**)&agg1, g_agg1);
    float* h2;   cudaGetSymbolAddress((void**)&h2,   g_h2);
    uint16_t* h1b; cudaGetSymbolAddress((void**)&h1b, g_h1b);
    uint16_t* h2b; cudaGetSymbolAddress((void**)&h2b, g_h2b);
    uint32_t* w1t; cudaGetSymbolAddress((void**)&w1t, g_w1t);
    uint32_t* w2t; cudaGetSymbolAddress((void**)&w2t, g_w2t);

    constexpr int STRB = 36 * 4;
    constexpr int SMEM1 = 3 * 128 * STRB + 3 * F_H  * STRB;  // 165888
    constexpr int SMEM2 = 3 * 128 * STRB + 3 * F_OUT * STRB; // 110592
    cudaFuncSetAttribute(k_gemm_mma<F_IN, F_H>,
                         cudaFuncAttributeMaxDynamicSharedMemorySize, SMEM1);
    cudaFuncSetAttribute(k_gemm_mma<F_H, F_OUT>,
                         cudaFuncAttributeMaxDynamicSharedMemorySize, SMEM2);

    const int MT1 = (N_NODES + 127) / 128;   // 391 (GEMM1 full)
    const int MT_C0 = C0_ROWS / 128;         // 196
    const int MT_C1 = (C1_ROWS + 127) / 128; // 195

    static cudaStream_t s_side = []() {
        cudaStream_t s; cudaStreamCreateWithFlags(&s, cudaStreamNonBlocking); return s;
    }();
    static cudaEvent_t ev_fork = []() {
        cudaEvent_t e; cudaEventCreateWithFlags(&e, cudaEventDisableTiming); return e;
    }();
    static cudaEvent_t ev_side = []() {
        cudaEvent_t e; cudaEventCreateWithFlags(&e, cudaEventDisableTiming); return e;
    }();
    static cudaEvent_t ev_g1 = []() {
        cudaEvent_t e; cudaEventCreateWithFlags(&e, cudaEventDisableTiming); return e;
    }();
    static cudaEvent_t ev_c1 = []() {
        cudaEvent_t e; cudaEventCreateWithFlags(&e, cudaEventDisableTiming); return e;
    }();

    // ---- fork ----
    cudaEventRecord(ev_fork, 0);
    cudaStreamWaitEvent(s_side, ev_fork, 0);

    // side chain: dropout mask + CSR build + W2 prep (all index-/weight-only)
    k_mask<<<(N_NODES * F_H) / 256, 256, 0, s_side>>>();
    k_detect<<<1, 1024, 0, s_side>>>((const int*)ei);
    k_zero<<<(N_NODES + 255) / 256, 256, 0, s_side>>>();
    k_degree<<<(E_EDGES + 255) / 256, 256, 0, s_side>>>(ei);
    k_scan1<<<SCAN_NB, SCAN_B, 0, s_side>>>();
    k_scan2<<<1, 64, 0, s_side>>>();
    k_scan3<<<(N_NODES + 255) / 256, 256, 0, s_side>>>();
    k_fill<<<(E_EDGES + 255) / 256, 256, 0, s_side>>>(ei);
    k_wprep<F_H, F_OUT><<<(F_H * F_OUT + 255) / 256, 256, 0, s_side>>>(W2, w2t);
    cudaEventRecord(ev_side, s_side);

    // main chain: W1 prep + GEMM1 (full M)
    k_wprep<F_IN, F_H><<<(F_IN * F_H + 255) / 256, 256>>>(W1, w1t);
    k_gemm_mma<F_IN, F_H><<<MT1, 512, SMEM1>>>(x, w1t, h1, h1b, N_NODES, 0);
    cudaEventRecord(ev_g1, 0);

    // side: chunk1 of layer1-agg + GEMM2 (needs GEMM1 + its own CSR/mask/W2)
    cudaStreamWaitEvent(s_side, ev_g1, 0);
    k_agg1<<<(C1_ROWS + 7) / 8, 256, 0, s_side>>>(b1, C0_ROWS, C1_ROWS);
    k_gemm_mma<F_H, F_OUT><<<MT_C1, 512, SMEM2, s_side>>>(agg1, w2t, h2, h2b, N_NODES, C0_ROWS);
    cudaEventRecord(ev_c1, s_side);

    // main: chunk0 (needs CSR/mask from side + GEMM1 in-stream)
    cudaStreamWaitEvent(0, ev_side, 0);
    k_agg1<<<(C0_ROWS + 7) / 8, 256>>>(b1, 0, C0_ROWS);
    k_gemm_mma<F_H, F_OUT><<<MT_C0, 512, SMEM2>>>(agg1, w2t, h2, h2b, N_NODES, 0);

    // join: agg2 needs both h2 chunks
    cudaStreamWaitEvent(0, ev_c1, 0);
    k_agg2<<<(N_NODES + 7) / 8, 256>>>(b2, out);
}

// round 13
// speedup vs baseline: 1.1054x; 1.1054x over previous
#include <cuda_runtime.h>
#include <cstdint>

// ---------------- problem constants ----------------
#define N_NODES 50000
#define F_IN    512
#define F_H     256
#define F_OUT   128
#define E_EDGES 800000
#define SCAN_B  1024
#define SCAN_NB ((N_NODES + SCAN_B - 1) / SCAN_B)   // 49

// ---------------- scratch (static device globals; no runtime alloc) --------
__device__ int   g_is64;
__device__ int   g_deg [N_NODES];
__device__ int   g_cursor[N_NODES];
__device__ int   g_rowstart[N_NODES + 1];
__device__ int   g_bsum[SCAN_NB];
__device__ int   g_csrc[E_EDGES];
__device__ float g_dinv[N_NODES];
__device__ uint16_t g_h1b[(size_t)N_NODES * F_H];    // bf16 h1 (sole copy)
__device__ float g_agg1[(size_t)N_NODES * F_H];
__device__ uint16_t g_h2b[(size_t)N_NODES * F_OUT];  // bf16 h2 (sole copy)
__device__ uint32_t g_w1t[F_IN * F_H];
__device__ uint32_t g_w2t[F_H * F_OUT];

// ---------------- helpers ----------------
__device__ __forceinline__ uint32_t f2tf32(float f) {
    uint32_t r; asm("cvt.rna.tf32.f32 %0, %1;" : "=r"(r) : "f"(f)); return r;
}
__device__ __forceinline__ uint32_t pack_bf16x2(float lo, float hi) {
    uint32_t r; asm("cvt.rn.bf16x2.f32 %0, %1, %2;" : "=r"(r) : "f"(hi), "f"(lo)); return r;
}
__device__ __forceinline__ float bf_lo(uint32_t u) { return __uint_as_float(u << 16); }
__device__ __forceinline__ float bf_hi(uint32_t u) { return __uint_as_float(u & 0xffff0000u); }
__device__ __forceinline__ uint32_t smem_u32(const void* p) {
    uint32_t a;
    asm("{ .reg .u64 t; cvta.to.shared.u64 t, %1; cvt.u32.u64 %0, t; }" : "=r"(a) : "l"(p));
    return a;
}
__device__ __forceinline__ void cp16(uint32_t s, const void* g) {
    asm volatile("cp.async.cg.shared.global [%0], [%1], 16;" :: "r"(s), "l"(g));
}
__device__ __forceinline__ void cp_commit() {
    asm volatile("cp.async.commit_group;" ::: "memory");
}
template <int N>
__device__ __forceinline__ void cp_wait() {
    asm volatile("cp.async.wait_group %0;" :: "n"(N) : "memory");
}

// ---------------- edge index access (int32 or int64) ----------------
__device__ __forceinline__ int edge_at(const void* ei, long long i) {
    if (g_is64) return (int)((const long long*)ei)[i];
    return ((const int*)ei)[i];
}
__global__ void k_detect(const int* ei32) {
    __shared__ int any_nonzero;
    if (threadIdx.x == 0) any_nonzero = 0;
    __syncthreads();
    if (ei32[2 * threadIdx.x + 1] != 0) atomicOr(&any_nonzero, 1);
    __syncthreads();
    if (threadIdx.x == 0) g_is64 = (any_nonzero == 0) ? 1 : 0;
}

// ---------------- degree / CSR ----------------
__global__ void k_zero() {
    int i = blockIdx.x * blockDim.x + threadIdx.x;
    if (i < N_NODES) g_deg[i] = 0;
}
__global__ void k_degree(const void* ei) {
    int e = blockIdx.x * blockDim.x + threadIdx.x;
    if (e < E_EDGES) atomicAdd(&g_deg[edge_at(ei, (long long)E_EDGES + e)], 1);
}
__global__ void __launch_bounds__(SCAN_B) k_scan1() {
    __shared__ int ws[32];
    int i = blockIdx.x * SCAN_B + threadIdx.x;
    int lane = threadIdx.x & 31, warp = threadIdx.x >> 5;
    int v = (i < N_NODES) ? g_deg[i] : 0;
    if (i < N_NODES) g_dinv[i] = rsqrtf((float)(v + 1));
    int inc = v;
#pragma unroll
    for (int off = 1; off < 32; off <<= 1) {
        int y = __shfl_up_sync(0xffffffffu, inc, off);
        if (lane >= off) inc += y;
    }
    if (lane == 31) ws[warp] = inc;
    __syncthreads();
    if (warp == 0) {
        int s = ws[lane];
        int sinc = s;
#pragma unroll
        for (int off = 1; off < 32; off <<= 1) {
            int y = __shfl_up_sync(0xffffffffu, sinc, off);
            if (lane >= off) sinc += y;
        }
        ws[lane] = sinc - s;
        if (lane == 31) g_bsum[blockIdx.x] = sinc;
    }
    __syncthreads();
    if (i < N_NODES) g_rowstart[i] = ws[warp] + inc - v;
}
__global__ void k_scan2() {
    __shared__ int s[SCAN_NB];
    if (threadIdx.x < SCAN_NB) s[threadIdx.x] = g_bsum[threadIdx.x];
    __syncthreads();
    if (threadIdx.x == 0) {
        int run = 0;
        for (int b = 0; b < SCAN_NB; b++) { int t = s[b]; s[b] = run; run += t; }
    }
    __syncthreads();
    if (threadIdx.x < SCAN_NB) g_bsum[threadIdx.x] = s[threadIdx.x];
}
__global__ void k_scan3() {
    int i = blockIdx.x * blockDim.x + threadIdx.x;
    if (i < N_NODES) {
        int rs = g_rowstart[i] + g_bsum[i >> 10];
        g_rowstart[i] = rs;
        g_cursor[i]   = rs;
    }
    if (i == 0) g_rowstart[N_NODES] = E_EDGES;
}
__global__ void k_fill(const void* ei) {
    int e = blockIdx.x * blockDim.x + threadIdx.x;
    if (e >= E_EDGES) return;
    int src = edge_at(ei, e);
    int dst = edge_at(ei, (long long)E_EDGES + e);
    int pos = atomicAdd(&g_cursor[dst], 1);
    g_csrc[pos] = src;
}

// ---------------- W prep ----------------
template <int Kd, int Nd>
__global__ void k_wprep(const float* __restrict__ W, uint32_t* __restrict__ Wt) {
    int i = blockIdx.x * blockDim.x + threadIdx.x;
    if (i >= Kd * Nd) return;
    int k = i / Nd, n = i % Nd;
    Wt[(size_t)n * Kd + k] = f2tf32(W[i]);
}

// ---------------- tensor-core GEMM via mma.sync (tf32), cp.async x3 -------
// Cb[M,Nd] (bf16) = A[M,Kd] * Bt[Nd,Kd]^T.
template <int Kd, int Nd>
__global__ void __launch_bounds__(512) k_gemm_mma(const float* __restrict__ A,
                                                  const uint32_t* __restrict__ Bt,
                                                  uint16_t* __restrict__ Cb, int M) {
    constexpr int WN  = Nd / 8;
    constexpr int NT  = WN / 8;
    constexpr int STR = 36;
    constexpr int ABYTES = 128 * STR * 4;
    constexpr int BBYTES = Nd * STR * 4;
    constexpr int KT = Kd / 32;
    extern __shared__ char smem[];
    const uint32_t sb = smem_u32(smem);

    const int t    = threadIdx.x;
    const int lane = t & 31, wid = t >> 5;
    const int gid  = lane >> 2, tig = lane & 3;
    const int wm   = (wid & 1) * 64;
    const int wn   = (wid >> 1) * WN;
    const int brow = blockIdx.x * 128;

    auto load_tile = [&](int kt, int buf) {
        uint32_t sA = sb + buf * ABYTES;
        uint32_t sB = sb + 3 * ABYTES + buf * BBYTES;
#pragma unroll
        for (int it = 0; it < 2; it++) {
            int f4 = it * 512 + t;
            int row = f4 >> 3, cq = f4 & 7;
            int grow = brow + row; if (grow > M - 1) grow = M - 1;
            cp16(sA + (uint32_t)(row * STR + cq * 4) * 4,
                 A + (size_t)grow * Kd + kt * 32 + cq * 4);
        }
#pragma unroll
        for (int it = 0; it < Nd / 64; it++) {
            int f4 = it * 512 + t;
            int n = f4 >> 3, cq = f4 & 7;
            cp16(sB + (uint32_t)(n * STR + cq * 4) * 4,
                 Bt + (size_t)n * Kd + kt * 32 + cq * 4);
        }
        cp_commit();
    };

    float c[4][NT][4];
#pragma unroll
    for (int mt = 0; mt < 4; mt++)
#pragma unroll
        for (int nt = 0; nt < NT; nt++)
#pragma unroll
            for (int i = 0; i < 4; i++) c[mt][nt][i] = 0.0f;

    load_tile(0, 0);
    load_tile(1, 1);
    for (int kt = 0; kt < KT; kt++) {
        int buf = kt % 3;
        if (kt + 2 < KT) { load_tile(kt + 2, (kt + 2) % 3); cp_wait<2>(); }
        else if (kt + 1 < KT) { cp_wait<1>(); }
        else { cp_wait<0>(); }
        __syncthreads();
        const uint32_t* As = (const uint32_t*)(smem + buf * ABYTES);
        const uint32_t* Bs = (const uint32_t*)(smem + 3 * ABYTES + buf * BBYTES);
#pragma unroll
        for (int ks = 0; ks < 4; ks++) {
            uint32_t a[4][4], b[NT][2];
#pragma unroll
            for (int mt = 0; mt < 4; mt++) {
                int r = wm + mt * 16;
                a[mt][0] = As[(r + gid)     * STR + ks * 8 + tig];
                a[mt][1] = As[(r + gid + 8) * STR + ks * 8 + tig];
                a[mt][2] = As[(r + gid)     * STR + ks * 8 + tig + 4];
                a[mt][3] = As[(r + gid + 8) * STR + ks * 8 + tig + 4];
            }
#pragma unroll
            for (int nt = 0; nt < NT; nt++) {
                int n = wn + nt * 8 + gid;
                b[nt][0] = Bs[n * STR + ks * 8 + tig];
                b[nt][1] = Bs[n * STR + ks * 8 + tig + 4];
            }
#pragma unroll
            for (int mt = 0; mt < 4; mt++)
#pragma unroll
                for (int nt = 0; nt < NT; nt++)
                    asm volatile(
                        "mma.sync.aligned.m16n8k8.row.col.f32.tf32.tf32.f32 "
                        "{%0,%1,%2,%3}, {%4,%5,%6,%7}, {%8,%9}, {%0,%1,%2,%3};"
                        : "+f"(c[mt][nt][0]), "+f"(c[mt][nt][1]),
                          "+f"(c[mt][nt][2]), "+f"(c[mt][nt][3])
                        : "r"(a[mt][0]), "r"(a[mt][1]), "r"(a[mt][2]), "r"(a[mt][3]),
                          "r"(b[nt][0]), "r"(b[nt][1]));
        }
        __syncthreads();
    }

#pragma unroll
    for (int mt = 0; mt < 4; mt++)
#pragma unroll
        for (int nt = 0; nt < NT; nt++) {
            int col = wn + nt * 8 + tig * 2;
            int r0  = brow + wm + mt * 16 + gid;
            int r1  = r0 + 8;
            if (r0 < M)
                *(uint32_t*)(Cb + (size_t)r0 * Nd + col) = pack_bf16x2(c[mt][nt][0], c[mt][nt][1]);
            if (r1 < M)
                *(uint32_t*)(Cb + (size_t)r1 * Nd + col) = pack_bf16x2(c[mt][nt][2], c[mt][nt][3]);
        }
}

// ---------------- threefry2x32 key (0,42) ----------------
__device__ __forceinline__ void threefry_0_42(unsigned c0, unsigned c1,
                                              unsigned& o0, unsigned& o1) {
    const unsigned ks0 = 0u, ks1 = 42u, ks2 = 0u ^ 42u ^ 0x1BD11BDAu;
    unsigned x0 = c0 + ks0, x1 = c1 + ks1;
#define TF_RND(r) { x0 += x1; x1 = __funnelshift_l(x1, x1, (r)); x1 ^= x0; }
    TF_RND(13) TF_RND(15) TF_RND(26) TF_RND(6)
    x0 += ks1; x1 += ks2 + 1u;
    TF_RND(17) TF_RND(29) TF_RND(16) TF_RND(24)
    x0 += ks2; x1 += ks0 + 2u;
    TF_RND(13) TF_RND(15) TF_RND(26) TF_RND(6)
    x0 += ks0; x1 += ks1 + 3u;
    TF_RND(17) TF_RND(29) TF_RND(16) TF_RND(24)
    x0 += ks1; x1 += ks2 + 4u;
    TF_RND(13) TF_RND(15) TF_RND(26) TF_RND(6)
    x0 += ks2; x1 += ks0 + 5u;
#undef TF_RND
    o0 = x0; o1 = x1;
}
__device__ __forceinline__ float tf_uniform(unsigned i) {
    unsigned r0, r1;
    threefry_0_42(0u, i, r0, r1);
    unsigned bits = r0 ^ r1;
    return __uint_as_float((bits >> 9) | 0x3f800000u) - 1.0f;
}

// ---------------- layer1 pull-agg: agg1 = dropout(relu(Â h1 + b1)) ---------
// 32 threads per node, 8 cols each; all terms from bf16 h1.
__global__ void __launch_bounds__(256) k_agg1(const float* __restrict__ b1) {
    int g    = threadIdx.x >> 5;
    int lane = threadIdx.x & 31;
    int node = blockIdx.x * 8 + g;
    if (node >= N_NODES) return;

    float dn = g_dinv[node];
    float s = dn * dn;
    uint4 rs = ((const uint4*)(g_h1b + (size_t)node * F_H))[lane];
    float acc[8] = {bf_lo(rs.x) * s, bf_hi(rs.x) * s, bf_lo(rs.y) * s, bf_hi(rs.y) * s,
                    bf_lo(rs.z) * s, bf_hi(rs.z) * s, bf_lo(rs.w) * s, bf_hi(rs.w) * s};

    int e0 = g_rowstart[node], e1 = g_rowstart[node + 1];
    int j = e0;
    for (; j + 2 <= e1; j += 2) {
        int s0 = g_csrc[j], s1 = g_csrc[j + 1];
        float n0 = dn * g_dinv[s0], n1 = dn * g_dinv[s1];
        uint4 r0 = ((const uint4*)(g_h1b + (size_t)s0 * F_H))[lane];
        uint4 r1 = ((const uint4*)(g_h1b + (size_t)s1 * F_H))[lane];
        acc[0] = fmaf(n0, bf_lo(r0.x), acc[0]); acc[1] = fmaf(n0, bf_hi(r0.x), acc[1]);
        acc[2] = fmaf(n0, bf_lo(r0.y), acc[2]); acc[3] = fmaf(n0, bf_hi(r0.y), acc[3]);
        acc[4] = fmaf(n0, bf_lo(r0.z), acc[4]); acc[5] = fmaf(n0, bf_hi(r0.z), acc[5]);
        acc[6] = fmaf(n0, bf_lo(r0.w), acc[6]); acc[7] = fmaf(n0, bf_hi(r0.w), acc[7]);
        acc[0] = fmaf(n1, bf_lo(r1.x), acc[0]); acc[1] = fmaf(n1, bf_hi(r1.x), acc[1]);
        acc[2] = fmaf(n1, bf_lo(r1.y), acc[2]); acc[3] = fmaf(n1, bf_hi(r1.y), acc[3]);
        acc[4] = fmaf(n1, bf_lo(r1.z), acc[4]); acc[5] = fmaf(n1, bf_hi(r1.z), acc[5]);
        acc[6] = fmaf(n1, bf_lo(r1.w), acc[6]); acc[7] = fmaf(n1, bf_hi(r1.w), acc[7]);
    }
    if (j < e1) {
        int s0 = g_csrc[j];
        float n0 = dn * g_dinv[s0];
        uint4 r0 = ((const uint4*)(g_h1b + (size_t)s0 * F_H))[lane];
        acc[0] = fmaf(n0, bf_lo(r0.x), acc[0]); acc[1] = fmaf(n0, bf_hi(r0.x), acc[1]);
        acc[2] = fmaf(n0, bf_lo(r0.y), acc[2]); acc[3] = fmaf(n0, bf_hi(r0.y), acc[3]);
        acc[4] = fmaf(n0, bf_lo(r0.z), acc[4]); acc[5] = fmaf(n0, bf_hi(r0.z), acc[5]);
        acc[6] = fmaf(n0, bf_lo(r0.w), acc[6]); acc[7] = fmaf(n0, bf_hi(r0.w), acc[7]);
    }
    const float4 bb0 = ((const float4*)b1)[lane * 2];
    const float4 bb1 = ((const float4*)b1)[lane * 2 + 1];
    float bias[8] = {bb0.x, bb0.y, bb0.z, bb0.w, bb1.x, bb1.y, bb1.z, bb1.w};
    unsigned i0 = (unsigned)node * F_H + lane * 8;
    float outv[8];
#pragma unroll
    for (int q = 0; q < 8; q++) {
        float v = fmaxf(acc[q] + bias[q], 0.0f);
        outv[q] = (tf_uniform(i0 + q) < 0.8f) ? v * 1.25f : 0.0f;
    }
    float4* dst = (float4*)(g_agg1 + (size_t)node * F_H);
    dst[lane * 2]     = make_float4(outv[0], outv[1], outv[2], outv[3]);
    dst[lane * 2 + 1] = make_float4(outv[4], outv[5], outv[6], outv[7]);
}

// ---------------- layer2 pull-agg + bias + softmax -> d_out ----------------
__global__ void __launch_bounds__(256) k_agg2(const float* __restrict__ b2,
                                              float* __restrict__ out) {
    int g    = threadIdx.x >> 5;
    int lane = threadIdx.x & 31;
    int node = blockIdx.x * 8 + g;
    if (node >= N_NODES) return;

    float dn = g_dinv[node];
    float s = dn * dn;
    uint2 rs = ((const uint2*)(g_h2b + (size_t)node * F_OUT))[lane];
    float4 acc = make_float4(bf_lo(rs.x) * s, bf_hi(rs.x) * s,
                             bf_lo(rs.y) * s, bf_hi(rs.y) * s);

    int e0 = g_rowstart[node], e1 = g_rowstart[node + 1];
    int j = e0;
    for (; j + 2 <= e1; j += 2) {
        int s0 = g_csrc[j], s1 = g_csrc[j + 1];
        float n0 = dn * g_dinv[s0], n1 = dn * g_dinv[s1];
        uint2 r0 = ((const uint2*)(g_h2b + (size_t)s0 * F_OUT))[lane];
        uint2 r1 = ((const uint2*)(g_h2b + (size_t)s1 * F_OUT))[lane];
        acc.x = fmaf(n0, bf_lo(r0.x), acc.x); acc.y = fmaf(n0, bf_hi(r0.x), acc.y);
        acc.z = fmaf(n0, bf_lo(r0.y), acc.z); acc.w = fmaf(n0, bf_hi(r0.y), acc.w);
        acc.x = fmaf(n1, bf_lo(r1.x), acc.x); acc.y = fmaf(n1, bf_hi(r1.x), acc.y);
        acc.z = fmaf(n1, bf_lo(r1.y), acc.z); acc.w = fmaf(n1, bf_hi(r1.y), acc.w);
    }
    if (j < e1) {
        int s0 = g_csrc[j];
        float n0 = dn * g_dinv[s0];
        uint2 r0 = ((const uint2*)(g_h2b + (size_t)s0 * F_OUT))[lane];
        acc.x = fmaf(n0, bf_lo(r0.x), acc.x); acc.y = fmaf(n0, bf_hi(r0.x), acc.y);
        acc.z = fmaf(n0, bf_lo(r0.y), acc.z); acc.w = fmaf(n0, bf_hi(r0.y), acc.w);
    }
    float4 bb = ((const float4*)b2)[lane];
    acc.x += bb.x; acc.y += bb.y; acc.z += bb.z; acc.w += bb.w;

    float m = fmaxf(fmaxf(acc.x, acc.y), fmaxf(acc.z, acc.w));
#pragma unroll
    for (int off = 16; off > 0; off >>= 1)
        m = fmaxf(m, __shfl_xor_sync(0xffffffffu, m, off));
    acc.x = expf(acc.x - m); acc.y = expf(acc.y - m);
    acc.z = expf(acc.z - m); acc.w = expf(acc.w - m);
    float sum = acc.x + acc.y + acc.z + acc.w;
#pragma unroll
    for (int off = 16; off > 0; off >>= 1)
        sum += __shfl_xor_sync(0xffffffffu, sum, off);
    float inv = 1.0f / sum;
    acc.x *= inv; acc.y *= inv; acc.z *= inv; acc.w *= inv;
    ((float4*)(out + (size_t)node * F_OUT))[lane] = acc;
}

// ---------------- launcher (R11 fork-join topology) ----------
extern "C" void kernel_launch(void* const* d_in, const int* in_sizes, int n_in,
                              void* d_out, int out_size) {
    const float* x  = (const float*)d_in[0];
    const void*  ei = d_in[1];
    const float* W1 = (const float*)d_in[2];
    const float* b1 = (const float*)d_in[3];
    const float* W2 = (const float*)d_in[4];
    const float* b2 = (const float*)d_in[5];
    float* out = (float*)d_out;

    float* agg1; cudaGetSymbolAddress((void**)&agg1, g_agg1);
    uint16_t* h1b; cudaGetSymbolAddress((void**)&h1b, g_h1b);
    uint16_t* h2b; cudaGetSymbolAddress((void**)&h2b, g_h2b);
    uint32_t* w1t; cudaGetSymbolAddress((void**)&w1t, g_w1t);
    uint32_t* w2t; cudaGetSymbolAddress((void**)&w2t, g_w2t);

    constexpr int STRB = 36 * 4;
    constexpr int SMEM1 = 3 * 128 * STRB + 3 * F_H  * STRB;  // 165888
    constexpr int SMEM2 = 3 * 128 * STRB + 3 * F_OUT * STRB; // 110592
    cudaFuncSetAttribute(k_gemm_mma<F_IN, F_H>,
                         cudaFuncAttributeMaxDynamicSharedMemorySize, SMEM1);
    cudaFuncSetAttribute(k_gemm_mma<F_H, F_OUT>,
                         cudaFuncAttributeMaxDynamicSharedMemorySize, SMEM2);

    const int MTILES = (N_NODES + 127) / 128;  // 391

    static cudaStream_t s_side = []() {
        cudaStream_t s; cudaStreamCreateWithFlags(&s, cudaStreamNonBlocking); return s;
    }();
    static cudaEvent_t ev_fork = []() {
        cudaEvent_t e; cudaEventCreateWithFlags(&e, cudaEventDisableTiming); return e;
    }();
    static cudaEvent_t ev_join = []() {
        cudaEvent_t e; cudaEventCreateWithFlags(&e, cudaEventDisableTiming); return e;
    }();

    // ---- fork: side stream builds CSR + W2 prep; main runs wprep1+GEMM1 ----
    cudaEventRecord(ev_fork, 0);
    cudaStreamWaitEvent(s_side, ev_fork, 0);

    k_detect<<<1, 1024, 0, s_side>>>((const int*)ei);
    k_zero<<<(N_NODES + 255) / 256, 256, 0, s_side>>>();
    k_degree<<<(E_EDGES + 255) / 256, 256, 0, s_side>>>(ei);
    k_scan1<<<SCAN_NB, SCAN_B, 0, s_side>>>();
    k_scan2<<<1, 64, 0, s_side>>>();
    k_scan3<<<(N_NODES + 255) / 256, 256, 0, s_side>>>();
    k_fill<<<(E_EDGES + 255) / 256, 256, 0, s_side>>>(ei);
    k_wprep<F_H, F_OUT><<<(F_H * F_OUT + 255) / 256, 256, 0, s_side>>>(W2, w2t);
    cudaEventRecord(ev_join, s_side);

    k_wprep<F_IN, F_H><<<(F_IN * F_H + 255) / 256, 256>>>(W1, w1t);
    k_gemm_mma<F_IN, F_H><<<MTILES, 512, SMEM1>>>(x, w1t, h1b, N_NODES);

    // ---- join ----
    cudaStreamWaitEvent(0, ev_join, 0);
    k_agg1<<<(N_NODES + 7) / 8, 256>>>(b1);
    k_gemm_mma<F_H, F_OUT><<<MTILES, 512, SMEM2>>>(agg1, w2t, h2b, N_NODES);
    k_agg2<<<(N_NODES + 7) / 8, 256>>>(b2, out);
}

// round 14
// speedup vs baseline: 1.1899x; 1.0764x over previous
#include <cuda_runtime.h>
#include <cstdint>

// ---------------- problem constants ----------------
#define N_NODES 50000
#define F_IN    512
#define F_H     256
#define F_OUT   128
#define E_EDGES 800000
#define SCAN_B  1024
#define SCAN_NB ((N_NODES + SCAN_B - 1) / SCAN_B)   // 49

// ---------------- scratch (static device globals; no runtime alloc) --------
__device__ int   g_is64;
__device__ int   g_deg [N_NODES];
__device__ int   g_cursor[N_NODES];
__device__ int   g_rowstart[N_NODES + 1];
__device__ int   g_bsum[SCAN_NB];
__device__ int   g_csrc[E_EDGES];
__device__ float g_dinv[N_NODES];
__device__ uint16_t g_xb [(size_t)N_NODES * F_IN];   // bf16 copy of x
__device__ uint16_t g_h1b[(size_t)N_NODES * F_H];    // bf16 h1 (sole copy)
__device__ float g_agg1[(size_t)N_NODES * F_H];
__device__ uint16_t g_h2b[(size_t)N_NODES * F_OUT];  // bf16 h2 (sole copy)
__device__ uint16_t g_w1tb[F_IN * F_H];              // W1^T bf16 [N][K]
__device__ uint32_t g_w2t [F_H * F_OUT];             // W2^T tf32 [N][K]

// ---------------- helpers ----------------
__device__ __forceinline__ uint32_t f2tf32(float f) {
    uint32_t r; asm("cvt.rna.tf32.f32 %0, %1;" : "=r"(r) : "f"(f)); return r;
}
__device__ __forceinline__ uint32_t pack_bf16x2(float lo, float hi) {
    uint32_t r; asm("cvt.rn.bf16x2.f32 %0, %1, %2;" : "=r"(r) : "f"(hi), "f"(lo)); return r;
}
__device__ __forceinline__ float bf_lo(uint32_t u) { return __uint_as_float(u << 16); }
__device__ __forceinline__ float bf_hi(uint32_t u) { return __uint_as_float(u & 0xffff0000u); }
__device__ __forceinline__ uint32_t smem_u32(const void* p) {
    uint32_t a;
    asm("{ .reg .u64 t; cvta.to.shared.u64 t, %1; cvt.u32.u64 %0, t; }" : "=r"(a) : "l"(p));
    return a;
}
__device__ __forceinline__ void cp16(uint32_t s, const void* g) {
    asm volatile("cp.async.cg.shared.global [%0], [%1], 16;" :: "r"(s), "l"(g));
}
__device__ __forceinline__ void cp_commit() {
    asm volatile("cp.async.commit_group;" ::: "memory");
}
template <int N>
__device__ __forceinline__ void cp_wait() {
    asm volatile("cp.async.wait_group %0;" :: "n"(N) : "memory");
}

// ---------------- edge index access (int32 or int64) ----------------
__device__ __forceinline__ int edge_at(const void* ei, long long i) {
    if (g_is64) return (int)((const long long*)ei)[i];
    return ((const int*)ei)[i];
}

// ---------------- zero + dtype detect (fused) ----------------
__global__ void k_zero_detect(const int* ei32) {
    int i = blockIdx.x * blockDim.x + threadIdx.x;
    if (i < N_NODES) g_deg[i] = 0;
    if (blockIdx.x == 0) {
        __shared__ int nz[256];
        int acc = 0;
#pragma unroll
        for (int u = 0; u < 8; u++)
            acc |= ei32[2 * (threadIdx.x * 8 + u) + 1];
        nz[threadIdx.x] = acc;
        __syncthreads();
        for (int off = 128; off > 0; off >>= 1) {
            if (threadIdx.x < off) nz[threadIdx.x] |= nz[threadIdx.x + off];
            __syncthreads();
        }
        if (threadIdx.x == 0) g_is64 = (nz[0] == 0) ? 1 : 0;
    }
}
__global__ void k_degree(const void* ei) {
    int e = blockIdx.x * blockDim.x + threadIdx.x;
    if (e < E_EDGES) atomicAdd(&g_deg[edge_at(ei, (long long)E_EDGES + e)], 1);
}
__global__ void __launch_bounds__(SCAN_B) k_scan1() {
    __shared__ int ws[32];
    int i = blockIdx.x * SCAN_B + threadIdx.x;
    int lane = threadIdx.x & 31, warp = threadIdx.x >> 5;
    int v = (i < N_NODES) ? g_deg[i] : 0;
    if (i < N_NODES) g_dinv[i] = rsqrtf((float)(v + 1));
    int inc = v;
#pragma unroll
    for (int off = 1; off < 32; off <<= 1) {
        int y = __shfl_up_sync(0xffffffffu, inc, off);
        if (lane >= off) inc += y;
    }
    if (lane == 31) ws[warp] = inc;
    __syncthreads();
    if (warp == 0) {
        int s = ws[lane];
        int sinc = s;
#pragma unroll
        for (int off = 1; off < 32; off <<= 1) {
            int y = __shfl_up_sync(0xffffffffu, sinc, off);
            if (lane >= off) sinc += y;
        }
        ws[lane] = sinc - s;
        if (lane == 31) g_bsum[blockIdx.x] = sinc;
    }
    __syncthreads();
    if (i < N_NODES) g_rowstart[i] = ws[warp] + inc - v;
}
__global__ void k_scan2() {
    __shared__ int s[SCAN_NB];
    if (threadIdx.x < SCAN_NB) s[threadIdx.x] = g_bsum[threadIdx.x];
    __syncthreads();
    if (threadIdx.x == 0) {
        int run = 0;
        for (int b = 0; b < SCAN_NB; b++) { int t = s[b]; s[b] = run; run += t; }
    }
    __syncthreads();
    if (threadIdx.x < SCAN_NB) g_bsum[threadIdx.x] = s[threadIdx.x];
}
__global__ void k_scan3() {
    int i = blockIdx.x * blockDim.x + threadIdx.x;
    if (i < N_NODES) {
        int rs = g_rowstart[i] + g_bsum[i >> 10];
        g_rowstart[i] = rs;
        g_cursor[i]   = rs;
    }
    if (i == 0) g_rowstart[N_NODES] = E_EDGES;
}
__global__ void k_fill(const void* ei) {
    int e = blockIdx.x * blockDim.x + threadIdx.x;
    if (e >= E_EDGES) return;
    int src = edge_at(ei, e);
    int dst = edge_at(ei, (long long)E_EDGES + e);
    int pos = atomicAdd(&g_cursor[dst], 1);
    g_csrc[pos] = src;
}

// ---------------- x -> bf16 convert (8 floats / thread) ----------------
__global__ void k_xconv(const float* __restrict__ x) {
    long long i = (long long)blockIdx.x * blockDim.x + threadIdx.x;
    const long long total = (long long)N_NODES * F_IN / 8;
    if (i >= total) return;
    float4 v0 = ((const float4*)x)[i * 2];
    float4 v1 = ((const float4*)x)[i * 2 + 1];
    uint4 o;
    o.x = pack_bf16x2(v0.x, v0.y);
    o.y = pack_bf16x2(v0.z, v0.w);
    o.z = pack_bf16x2(v1.x, v1.y);
    o.w = pack_bf16x2(v1.z, v1.w);
    ((uint4*)g_xb)[i] = o;
}

// ---------------- W preps ----------------
__global__ void k_wprep1(const float* __restrict__ W) {      // -> bf16 [N][K]
    int i = blockIdx.x * blockDim.x + threadIdx.x;
    if (i >= F_IN * F_H) return;
    int k = i / F_H, n = i % F_H;
    g_w1tb[(size_t)n * F_IN + k] = (uint16_t)(pack_bf16x2(W[i], 0.0f) & 0xffffu);
}
__global__ void k_wprep2(const float* __restrict__ W) {      // -> tf32 [N][K]
    int i = blockIdx.x * blockDim.x + threadIdx.x;
    if (i >= F_H * F_OUT) return;
    int k = i / F_OUT, n = i % F_OUT;
    g_w2t[(size_t)n * F_H + k] = f2tf32(W[i]);
}

// ---------------- bf16 GEMM via mma.sync m16n8k16, cp.async x3 ------------
// Cb[M,Nd](bf16) = A[M,Kd](bf16) * Bt[Nd,Kd](bf16)^T.  BK=64 elements.
template <int Kd, int Nd>
__global__ void __launch_bounds__(512) k_gemm_bf16(const uint16_t* __restrict__ A,
                                                   const uint16_t* __restrict__ Bt,
                                                   uint16_t* __restrict__ Cb, int M) {
    constexpr int WN  = Nd / 8;
    constexpr int NT  = WN / 8;
    constexpr int STR = 36;                        // words per row (128B data + 16B pad)
    constexpr int ABYTES = 128 * STR * 4;
    constexpr int BBYTES = Nd * STR * 4;
    constexpr int KT = Kd / 64;
    extern __shared__ char smem[];
    const uint32_t sb = smem_u32(smem);

    const int t    = threadIdx.x;
    const int lane = t & 31, wid = t >> 5;
    const int gid  = lane >> 2, tig = lane & 3;
    const int wm   = (wid & 1) * 64;
    const int wn   = (wid >> 1) * WN;
    const int brow = blockIdx.x * 128;

    auto load_tile = [&](int kt, int buf) {
        uint32_t sA = sb + buf * ABYTES;
        uint32_t sB = sb + 3 * ABYTES + buf * BBYTES;
#pragma unroll
        for (int it = 0; it < 2; it++) {
            int f4 = it * 512 + t;                 // 0..1023
            int row = f4 >> 3, cq = f4 & 7;        // 8 x 16B chunks per 128B row
            int grow = brow + row; if (grow > M - 1) grow = M - 1;
            cp16(sA + (uint32_t)(row * STR + cq * 4) * 4,
                 A + (size_t)grow * Kd + kt * 64 + cq * 8);
        }
#pragma unroll
        for (int it = 0; it < Nd / 64; it++) {
            int f4 = it * 512 + t;
            int n = f4 >> 3, cq = f4 & 7;
            cp16(sB + (uint32_t)(n * STR + cq * 4) * 4,
                 Bt + (size_t)n * Kd + kt * 64 + cq * 8);
        }
        cp_commit();
    };

    float c[4][NT][4];
#pragma unroll
    for (int mt = 0; mt < 4; mt++)
#pragma unroll
        for (int nt = 0; nt < NT; nt++)
#pragma unroll
            for (int i = 0; i < 4; i++) c[mt][nt][i] = 0.0f;

    load_tile(0, 0);
    load_tile(1, 1);
    for (int kt = 0; kt < KT; kt++) {
        int buf = kt % 3;
        if (kt + 2 < KT) { load_tile(kt + 2, (kt + 2) % 3); cp_wait<2>(); }
        else if (kt + 1 < KT) { cp_wait<1>(); }
        else { cp_wait<0>(); }
        __syncthreads();
        const uint32_t* As = (const uint32_t*)(smem + buf * ABYTES);
        const uint32_t* Bs = (const uint32_t*)(smem + 3 * ABYTES + buf * BBYTES);
#pragma unroll
        for (int ks = 0; ks < 4; ks++) {           // K=16 per step
            uint32_t a[4][4], b[NT][2];
#pragma unroll
            for (int mt = 0; mt < 4; mt++) {
                int r = wm + mt * 16;
                a[mt][0] = As[(r + gid)     * STR + ks * 8 + tig];
                a[mt][1] = As[(r + gid + 8) * STR + ks * 8 + tig];
                a[mt][2] = As[(r + gid)     * STR + ks * 8 + tig + 4];
                a[mt][3] = As[(r + gid + 8) * STR + ks * 8 + tig + 4];
            }
#pragma unroll
            for (int nt = 0; nt < NT; nt++) {
                int n = wn + nt * 8 + gid;
                b[nt][0] = Bs[n * STR + ks * 8 + tig];
                b[nt][1] = Bs[n * STR + ks * 8 + tig + 4];
            }
#pragma unroll
            for (int mt = 0; mt < 4; mt++)
#pragma unroll
                for (int nt = 0; nt < NT; nt++)
                    asm volatile(
                        "mma.sync.aligned.m16n8k16.row.col.f32.bf16.bf16.f32 "
                        "{%0,%1,%2,%3}, {%4,%5,%6,%7}, {%8,%9}, {%0,%1,%2,%3};"
                        : "+f"(c[mt][nt][0]), "+f"(c[mt][nt][1]),
                          "+f"(c[mt][nt][2]), "+f"(c[mt][nt][3])
                        : "r"(a[mt][0]), "r"(a[mt][1]), "r"(a[mt][2]), "r"(a[mt][3]),
                          "r"(b[nt][0]), "r"(b[nt][1]));
        }
        __syncthreads();
    }

#pragma unroll
    for (int mt = 0; mt < 4; mt++)
#pragma unroll
        for (int nt = 0; nt < NT; nt++) {
            int col = wn + nt * 8 + tig * 2;
            int r0  = brow + wm + mt * 16 + gid;
            int r1  = r0 + 8;
            if (r0 < M)
                *(uint32_t*)(Cb + (size_t)r0 * Nd + col) = pack_bf16x2(c[mt][nt][0], c[mt][nt][1]);
            if (r1 < M)
                *(uint32_t*)(Cb + (size_t)r1 * Nd + col) = pack_bf16x2(c[mt][nt][2], c[mt][nt][3]);
        }
}

// ---------------- tf32 GEMM (unchanged; used for layer 2) -----------------
template <int Kd, int Nd>
__global__ void __launch_bounds__(512) k_gemm_mma(const float* __restrict__ A,
                                                  const uint32_t* __restrict__ Bt,
                                                  uint16_t* __restrict__ Cb, int M) {
    constexpr int WN  = Nd / 8;
    constexpr int NT  = WN / 8;
    constexpr int STR = 36;
    constexpr int ABYTES = 128 * STR * 4;
    constexpr int BBYTES = Nd * STR * 4;
    constexpr int KT = Kd / 32;
    extern __shared__ char smem[];
    const uint32_t sb = smem_u32(smem);

    const int t    = threadIdx.x;
    const int lane = t & 31, wid = t >> 5;
    const int gid  = lane >> 2, tig = lane & 3;
    const int wm   = (wid & 1) * 64;
    const int wn   = (wid >> 1) * WN;
    const int brow = blockIdx.x * 128;

    auto load_tile = [&](int kt, int buf) {
        uint32_t sA = sb + buf * ABYTES;
        uint32_t sB = sb + 3 * ABYTES + buf * BBYTES;
#pragma unroll
        for (int it = 0; it < 2; it++) {
            int f4 = it * 512 + t;
            int row = f4 >> 3, cq = f4 & 7;
            int grow = brow + row; if (grow > M - 1) grow = M - 1;
            cp16(sA + (uint32_t)(row * STR + cq * 4) * 4,
                 A + (size_t)grow * Kd + kt * 32 + cq * 4);
        }
#pragma unroll
        for (int it = 0; it < Nd / 64; it++) {
            int f4 = it * 512 + t;
            int n = f4 >> 3, cq = f4 & 7;
            cp16(sB + (uint32_t)(n * STR + cq * 4) * 4,
                 Bt + (size_t)n * Kd + kt * 32 + cq * 4);
        }
        cp_commit();
    };

    float c[4][NT][4];
#pragma unroll
    for (int mt = 0; mt < 4; mt++)
#pragma unroll
        for (int nt = 0; nt < NT; nt++)
#pragma unroll
            for (int i = 0; i < 4; i++) c[mt][nt][i] = 0.0f;

    load_tile(0, 0);
    load_tile(1, 1);
    for (int kt = 0; kt < KT; kt++) {
        int buf = kt % 3;
        if (kt + 2 < KT) { load_tile(kt + 2, (kt + 2) % 3); cp_wait<2>(); }
        else if (kt + 1 < KT) { cp_wait<1>(); }
        else { cp_wait<0>(); }
        __syncthreads();
        const uint32_t* As = (const uint32_t*)(smem + buf * ABYTES);
        const uint32_t* Bs = (const uint32_t*)(smem + 3 * ABYTES + buf * BBYTES);
#pragma unroll
        for (int ks = 0; ks < 4; ks++) {
            uint32_t a[4][4], b[NT][2];
#pragma unroll
            for (int mt = 0; mt < 4; mt++) {
                int r = wm + mt * 16;
                a[mt][0] = As[(r + gid)     * STR + ks * 8 + tig];
                a[mt][1] = As[(r + gid + 8) * STR + ks * 8 + tig];
                a[mt][2] = As[(r + gid)     * STR + ks * 8 + tig + 4];
                a[mt][3] = As[(r + gid + 8) * STR + ks * 8 + tig + 4];
            }
#pragma unroll
            for (int nt = 0; nt < NT; nt++) {
                int n = wn + nt * 8 + gid;
                b[nt][0] = Bs[n * STR + ks * 8 + tig];
                b[nt][1] = Bs[n * STR + ks * 8 + tig + 4];
            }
#pragma unroll
            for (int mt = 0; mt < 4; mt++)
#pragma unroll
                for (int nt = 0; nt < NT; nt++)
                    asm volatile(
                        "mma.sync.aligned.m16n8k8.row.col.f32.tf32.tf32.f32 "
                        "{%0,%1,%2,%3}, {%4,%5,%6,%7}, {%8,%9}, {%0,%1,%2,%3};"
                        : "+f"(c[mt][nt][0]), "+f"(c[mt][nt][1]),
                          "+f"(c[mt][nt][2]), "+f"(c[mt][nt][3])
                        : "r"(a[mt][0]), "r"(a[mt][1]), "r"(a[mt][2]), "r"(a[mt][3]),
                          "r"(b[nt][0]), "r"(b[nt][1]));
        }
        __syncthreads();
    }

#pragma unroll
    for (int mt = 0; mt < 4; mt++)
#pragma unroll
        for (int nt = 0; nt < NT; nt++) {
            int col = wn + nt * 8 + tig * 2;
            int r0  = brow + wm + mt * 16 + gid;
            int r1  = r0 + 8;
            if (r0 < M)
                *(uint32_t*)(Cb + (size_t)r0 * Nd + col) = pack_bf16x2(c[mt][nt][0], c[mt][nt][1]);
            if (r1 < M)
                *(uint32_t*)(Cb + (size_t)r1 * Nd + col) = pack_bf16x2(c[mt][nt][2], c[mt][nt][3]);
        }
}

// ---------------- threefry2x32 key (0,42) ----------------
__device__ __forceinline__ void threefry_0_42(unsigned c0, unsigned c1,
                                              unsigned& o0, unsigned& o1) {
    const unsigned ks0 = 0u, ks1 = 42u, ks2 = 0u ^ 42u ^ 0x1BD11BDAu;
    unsigned x0 = c0 + ks0, x1 = c1 + ks1;
#define TF_RND(r) { x0 += x1; x1 = __funnelshift_l(x1, x1, (r)); x1 ^= x0; }
    TF_RND(13) TF_RND(15) TF_RND(26) TF_RND(6)
    x0 += ks1; x1 += ks2 + 1u;
    TF_RND(17) TF_RND(29) TF_RND(16) TF_RND(24)
    x0 += ks2; x1 += ks0 + 2u;
    TF_RND(13) TF_RND(15) TF_RND(26) TF_RND(6)
    x0 += ks0; x1 += ks1 + 3u;
    TF_RND(17) TF_RND(29) TF_RND(16) TF_RND(24)
    x0 += ks1; x1 += ks2 + 4u;
    TF_RND(13) TF_RND(15) TF_RND(26) TF_RND(6)
    x0 += ks2; x1 += ks0 + 5u;
#undef TF_RND
    o0 = x0; o1 = x1;
}
__device__ __forceinline__ float tf_uniform(unsigned i) {
    unsigned r0, r1;
    threefry_0_42(0u, i, r0, r1);
    unsigned bits = r0 ^ r1;
    return __uint_as_float((bits >> 9) | 0x3f800000u) - 1.0f;
}

// ---------------- layer1 pull-agg: agg1 = dropout(relu(Â h1 + b1)) ---------
__global__ void __launch_bounds__(256) k_agg1(const float* __restrict__ b1) {
    int g    = threadIdx.x >> 5;
    int lane = threadIdx.x & 31;
    int node = blockIdx.x * 8 + g;
    if (node >= N_NODES) return;

    float dn = g_dinv[node];
    float s = dn * dn;
    uint4 rs = ((const uint4*)(g_h1b + (size_t)node * F_H))[lane];
    float acc[8] = {bf_lo(rs.x) * s, bf_hi(rs.x) * s, bf_lo(rs.y) * s, bf_hi(rs.y) * s,
                    bf_lo(rs.z) * s, bf_hi(rs.z) * s, bf_lo(rs.w) * s, bf_hi(rs.w) * s};

    int e0 = g_rowstart[node], e1 = g_rowstart[node + 1];
    int j = e0;
    for (; j + 2 <= e1; j += 2) {
        int s0 = g_csrc[j], s1 = g_csrc[j + 1];
        float n0 = dn * g_dinv[s0], n1 = dn * g_dinv[s1];
        uint4 r0 = ((const uint4*)(g_h1b + (size_t)s0 * F_H))[lane];
        uint4 r1 = ((const uint4*)(g_h1b + (size_t)s1 * F_H))[lane];
        acc[0] = fmaf(n0, bf_lo(r0.x), acc[0]); acc[1] = fmaf(n0, bf_hi(r0.x), acc[1]);
        acc[2] = fmaf(n0, bf_lo(r0.y), acc[2]); acc[3] = fmaf(n0, bf_hi(r0.y), acc[3]);
        acc[4] = fmaf(n0, bf_lo(r0.z), acc[4]); acc[5] = fmaf(n0, bf_hi(r0.z), acc[5]);
        acc[6] = fmaf(n0, bf_lo(r0.w), acc[6]); acc[7] = fmaf(n0, bf_hi(r0.w), acc[7]);
        acc[0] = fmaf(n1, bf_lo(r1.x), acc[0]); acc[1] = fmaf(n1, bf_hi(r1.x), acc[1]);
        acc[2] = fmaf(n1, bf_lo(r1.y), acc[2]); acc[3] = fmaf(n1, bf_hi(r1.y), acc[3]);
        acc[4] = fmaf(n1, bf_lo(r1.z), acc[4]); acc[5] = fmaf(n1, bf_hi(r1.z), acc[5]);
        acc[6] = fmaf(n1, bf_lo(r1.w), acc[6]); acc[7] = fmaf(n1, bf_hi(r1.w), acc[7]);
    }
    if (j < e1) {
        int s0 = g_csrc[j];
        float n0 = dn * g_dinv[s0];
        uint4 r0 = ((const uint4*)(g_h1b + (size_t)s0 * F_H))[lane];
        acc[0] = fmaf(n0, bf_lo(r0.x), acc[0]); acc[1] = fmaf(n0, bf_hi(r0.x), acc[1]);
        acc[2] = fmaf(n0, bf_lo(r0.y), acc[2]); acc[3] = fmaf(n0, bf_hi(r0.y), acc[3]);
        acc[4] = fmaf(n0, bf_lo(r0.z), acc[4]); acc[5] = fmaf(n0, bf_hi(r0.z), acc[5]);
        acc[6] = fmaf(n0, bf_lo(r0.w), acc[6]); acc[7] = fmaf(n0, bf_hi(r0.w), acc[7]);
    }
    const float4 bb0 = ((const float4*)b1)[lane * 2];
    const float4 bb1 = ((const float4*)b1)[lane * 2 + 1];
    float bias[8] = {bb0.x, bb0.y, bb0.z, bb0.w, bb1.x, bb1.y, bb1.z, bb1.w};
    unsigned i0 = (unsigned)node * F_H + lane * 8;
    float outv[8];
#pragma unroll
    for (int q = 0; q < 8; q++) {
        float v = fmaxf(acc[q] + bias[q], 0.0f);
        outv[q] = (tf_uniform(i0 + q) < 0.8f) ? v * 1.25f : 0.0f;
    }
    float4* dst = (float4*)(g_agg1 + (size_t)node * F_H);
    dst[lane * 2]     = make_float4(outv[0], outv[1], outv[2], outv[3]);
    dst[lane * 2 + 1] = make_float4(outv[4], outv[5], outv[6], outv[7]);
}

// ---------------- layer2 pull-agg + bias + softmax -> d_out ----------------
__global__ void __launch_bounds__(256) k_agg2(const float* __restrict__ b2,
                                              float* __restrict__ out) {
    int g    = threadIdx.x >> 5;
    int lane = threadIdx.x & 31;
    int node = blockIdx.x * 8 + g;
    if (node >= N_NODES) return;

    float dn = g_dinv[node];
    float s = dn * dn;
    uint2 rs = ((const uint2*)(g_h2b + (size_t)node * F_OUT))[lane];
    float4 acc = make_float4(bf_lo(rs.x) * s, bf_hi(rs.x) * s,
                             bf_lo(rs.y) * s, bf_hi(rs.y) * s);

    int e0 = g_rowstart[node], e1 = g_rowstart[node + 1];
    int j = e0;
    for (; j + 2 <= e1; j += 2) {
        int s0 = g_csrc[j], s1 = g_csrc[j + 1];
        float n0 = dn * g_dinv[s0], n1 = dn * g_dinv[s1];
        uint2 r0 = ((const uint2*)(g_h2b + (size_t)s0 * F_OUT))[lane];
        uint2 r1 = ((const uint2*)(g_h2b + (size_t)s1 * F_OUT))[lane];
        acc.x = fmaf(n0, bf_lo(r0.x), acc.x); acc.y = fmaf(n0, bf_hi(r0.x), acc.y);
        acc.z = fmaf(n0, bf_lo(r0.y), acc.z); acc.w = fmaf(n0, bf_hi(r0.y), acc.w);
        acc.x = fmaf(n1, bf_lo(r1.x), acc.x); acc.y = fmaf(n1, bf_hi(r1.x), acc.y);
        acc.z = fmaf(n1, bf_lo(r1.y), acc.z); acc.w = fmaf(n1, bf_hi(r1.y), acc.w);
    }
    if (j < e1) {
        int s0 = g_csrc[j];
        float n0 = dn * g_dinv[s0];
        uint2 r0 = ((const uint2*)(g_h2b + (size_t)s0 * F_OUT))[lane];
        acc.x = fmaf(n0, bf_lo(r0.x), acc.x); acc.y = fmaf(n0, bf_hi(r0.x), acc.y);
        acc.z = fmaf(n0, bf_lo(r0.y), acc.z); acc.w = fmaf(n0, bf_hi(r0.y), acc.w);
    }
    float4 bb = ((const float4*)b2)[lane];
    acc.x += bb.x; acc.y += bb.y; acc.z += bb.z; acc.w += bb.w;

    float m = fmaxf(fmaxf(acc.x, acc.y), fmaxf(acc.z, acc.w));
#pragma unroll
    for (int off = 16; off > 0; off >>= 1)
        m = fmaxf(m, __shfl_xor_sync(0xffffffffu, m, off));
    acc.x = expf(acc.x - m); acc.y = expf(acc.y - m);
    acc.z = expf(acc.z - m); acc.w = expf(acc.w - m);
    float sum = acc.x + acc.y + acc.z + acc.w;
#pragma unroll
    for (int off = 16; off > 0; off >>= 1)
        sum += __shfl_xor_sync(0xffffffffu, sum, off);
    float inv = 1.0f / sum;
    acc.x *= inv; acc.y *= inv; acc.z *= inv; acc.w *= inv;
    ((float4*)(out + (size_t)node * F_OUT))[lane] = acc;
}

// ---------------- launcher (fork-join; xconv overlaps CSR build) ----------
extern "C" void kernel_launch(void* const* d_in, const int* in_sizes, int n_in,
                              void* d_out, int out_size) {
    const float* x  = (const float*)d_in[0];
    const void*  ei = d_in[1];
    const float* W1 = (const float*)d_in[2];
    const float* b1 = (const float*)d_in[3];
    const float* W2 = (const float*)d_in[4];
    const float* b2 = (const float*)d_in[5];
    float* out = (float*)d_out;

    float* agg1; cudaGetSymbolAddress((void**)&agg1, g_agg1);
    uint16_t* xb;  cudaGetSymbolAddress((void**)&xb,  g_xb);
    uint16_t* h1b; cudaGetSymbolAddress((void**)&h1b, g_h1b);
    uint16_t* h2b; cudaGetSymbolAddress((void**)&h2b, g_h2b);
    uint16_t* w1tb; cudaGetSymbolAddress((void**)&w1tb, g_w1tb);
    uint32_t* w2t;  cudaGetSymbolAddress((void**)&w2t,  g_w2t);

    constexpr int STRB = 36 * 4;
    constexpr int SMEM1 = 3 * 128 * STRB + 3 * F_H  * STRB;  // 165888
    constexpr int SMEM2 = 3 * 128 * STRB + 3 * F_OUT * STRB; // 110592
    cudaFuncSetAttribute(k_gemm_bf16<F_IN, F_H>,
                         cudaFuncAttributeMaxDynamicSharedMemorySize, SMEM1);
    cudaFuncSetAttribute(k_gemm_mma<F_H, F_OUT>,
                         cudaFuncAttributeMaxDynamicSharedMemorySize, SMEM2);

    const int MTILES = (N_NODES + 127) / 128;  // 391

    static cudaStream_t s_side = []() {
        cudaStream_t s; cudaStreamCreateWithFlags(&s, cudaStreamNonBlocking); return s;
    }();
    static cudaEvent_t ev_fork = []() {
        cudaEvent_t e; cudaEventCreateWithFlags(&e, cudaEventDisableTiming); return e;
    }();
    static cudaEvent_t ev_join = []() {
        cudaEvent_t e; cudaEventCreateWithFlags(&e, cudaEventDisableTiming); return e;
    }();

    // ---- fork ----
    cudaEventRecord(ev_fork, 0);
    cudaStreamWaitEvent(s_side, ev_fork, 0);

    // side chain: CSR build + W2 prep
    k_zero_detect<<<(N_NODES + 255) / 256, 256, 0, s_side>>>((const int*)ei);
    k_degree<<<(E_EDGES + 255) / 256, 256, 0, s_side>>>(ei);
    k_scan1<<<SCAN_NB, SCAN_B, 0, s_side>>>();
    k_scan2<<<1, 64, 0, s_side>>>();
    k_scan3<<<(N_NODES + 255) / 256, 256, 0, s_side>>>();
    k_fill<<<(E_EDGES + 255) / 256, 256, 0, s_side>>>(ei);
    k_wprep2<<<(F_H * F_OUT + 255) / 256, 256, 0, s_side>>>(W2);
    cudaEventRecord(ev_join, s_side);

    // main chain: x->bf16, W1 prep, bf16 GEMM1
    k_xconv<<<(int)(((long long)N_NODES * F_IN / 8 + 255) / 256), 256>>>(x);
    k_wprep1<<<(F_IN * F_H + 255) / 256, 256>>>(W1);
    k_gemm_bf16<F_IN, F_H><<<MTILES, 512, SMEM1>>>(xb, w1tb, h1b, N_NODES);

    // ---- join ----
    cudaStreamWaitEvent(0, ev_join, 0);
    k_agg1<<<(N_NODES + 7) / 8, 256>>>(b1);
    k_gemm_mma<F_H, F_OUT><<<MTILES, 512, SMEM2>>>(agg1, w2t, h2b, N_NODES);
    k_agg2<<<(N_NODES + 7) / 8, 256>>>(b2, out);
}

// round 15
// speedup vs baseline: 1.2599x; 1.0589x over previous
#include <cuda_runtime.h>
#include <cstdint>

// ---------------- problem constants ----------------
#define N_NODES 50000
#define F_IN    512
#define F_H     256
#define F_OUT   128
#define E_EDGES 800000
#define SCAN_B  1024
#define SCAN_NB ((N_NODES + SCAN_B - 1) / SCAN_B)   // 49

// ---------------- scratch (static device globals; no runtime alloc) --------
__device__ int   g_is64;
__device__ int   g_deg [N_NODES];
__device__ int   g_cursor[N_NODES];
__device__ int   g_rowstart[N_NODES + 1];
__device__ int   g_bsum[SCAN_NB];
__device__ int   g_csrc[E_EDGES];
__device__ float g_dinv[N_NODES];
__device__ uint16_t g_xb   [(size_t)N_NODES * F_IN];  // bf16 copy of x
__device__ uint16_t g_h1b  [(size_t)N_NODES * F_H];   // bf16 h1
__device__ uint16_t g_agg1b[(size_t)N_NODES * F_H];   // bf16 agg1 (sole copy)
__device__ uint16_t g_h2b  [(size_t)N_NODES * F_OUT]; // bf16 h2
__device__ uint16_t g_w1tb[F_IN * F_H];               // W1^T bf16 [N][K]
__device__ uint16_t g_w2tb[F_H * F_OUT];              // W2^T bf16 [N][K]

// ---------------- helpers ----------------
__device__ __forceinline__ uint32_t pack_bf16x2(float lo, float hi) {
    uint32_t r; asm("cvt.rn.bf16x2.f32 %0, %1, %2;" : "=r"(r) : "f"(hi), "f"(lo)); return r;
}
__device__ __forceinline__ float bf_lo(uint32_t u) { return __uint_as_float(u << 16); }
__device__ __forceinline__ float bf_hi(uint32_t u) { return __uint_as_float(u & 0xffff0000u); }
__device__ __forceinline__ uint32_t smem_u32(const void* p) {
    uint32_t a;
    asm("{ .reg .u64 t; cvta.to.shared.u64 t, %1; cvt.u32.u64 %0, t; }" : "=r"(a) : "l"(p));
    return a;
}
__device__ __forceinline__ void cp16(uint32_t s, const void* g) {
    asm volatile("cp.async.cg.shared.global [%0], [%1], 16;" :: "r"(s), "l"(g));
}
__device__ __forceinline__ void cp_commit() {
    asm volatile("cp.async.commit_group;" ::: "memory");
}
template <int N>
__device__ __forceinline__ void cp_wait() {
    asm volatile("cp.async.wait_group %0;" :: "n"(N) : "memory");
}

// ---------------- edge index access (int32 or int64) ----------------
__device__ __forceinline__ int edge_at(const void* ei, long long i) {
    if (g_is64) return (int)((const long long*)ei)[i];
    return ((const int*)ei)[i];
}

// ---------------- zero + dtype detect (fused) ----------------
__global__ void k_zero_detect(const int* ei32) {
    int i = blockIdx.x * blockDim.x + threadIdx.x;
    if (i < N_NODES) g_deg[i] = 0;
    if (blockIdx.x == 0) {
        __shared__ int nz[256];
        int acc = 0;
#pragma unroll
        for (int u = 0; u < 8; u++)
            acc |= ei32[2 * (threadIdx.x * 8 + u) + 1];
        nz[threadIdx.x] = acc;
        __syncthreads();
        for (int off = 128; off > 0; off >>= 1) {
            if (threadIdx.x < off) nz[threadIdx.x] |= nz[threadIdx.x + off];
            __syncthreads();
        }
        if (threadIdx.x == 0) g_is64 = (nz[0] == 0) ? 1 : 0;
    }
}
__global__ void k_degree(const void* ei) {
    int e = blockIdx.x * blockDim.x + threadIdx.x;
    if (e < E_EDGES) atomicAdd(&g_deg[edge_at(ei, (long long)E_EDGES + e)], 1);
}
__global__ void __launch_bounds__(SCAN_B) k_scan1() {
    __shared__ int ws[32];
    int i = blockIdx.x * SCAN_B + threadIdx.x;
    int lane = threadIdx.x & 31, warp = threadIdx.x >> 5;
    int v = (i < N_NODES) ? g_deg[i] : 0;
    if (i < N_NODES) g_dinv[i] = rsqrtf((float)(v + 1));
    int inc = v;
#pragma unroll
    for (int off = 1; off < 32; off <<= 1) {
        int y = __shfl_up_sync(0xffffffffu, inc, off);
        if (lane >= off) inc += y;
    }
    if (lane == 31) ws[warp] = inc;
    __syncthreads();
    if (warp == 0) {
        int s = ws[lane];
        int sinc = s;
#pragma unroll
        for (int off = 1; off < 32; off <<= 1) {
            int y = __shfl_up_sync(0xffffffffu, sinc, off);
            if (lane >= off) sinc += y;
        }
        ws[lane] = sinc - s;
        if (lane == 31) g_bsum[blockIdx.x] = sinc;
    }
    __syncthreads();
    if (i < N_NODES) g_rowstart[i] = ws[warp] + inc - v;
}
__global__ void k_scan2() {
    __shared__ int s[SCAN_NB];
    if (threadIdx.x < SCAN_NB) s[threadIdx.x] = g_bsum[threadIdx.x];
    __syncthreads();
    if (threadIdx.x == 0) {
        int run = 0;
        for (int b = 0; b < SCAN_NB; b++) { int t = s[b]; s[b] = run; run += t; }
    }
    __syncthreads();
    if (threadIdx.x < SCAN_NB) g_bsum[threadIdx.x] = s[threadIdx.x];
}
__global__ void k_scan3() {
    int i = blockIdx.x * blockDim.x + threadIdx.x;
    if (i < N_NODES) {
        int rs = g_rowstart[i] + g_bsum[i >> 10];
        g_rowstart[i] = rs;
        g_cursor[i]   = rs;
    }
    if (i == 0) g_rowstart[N_NODES] = E_EDGES;
}
__global__ void k_fill(const void* ei) {
    int e = blockIdx.x * blockDim.x + threadIdx.x;
    if (e >= E_EDGES) return;
    int src = edge_at(ei, e);
    int dst = edge_at(ei, (long long)E_EDGES + e);
    int pos = atomicAdd(&g_cursor[dst], 1);
    g_csrc[pos] = src;
}

// ---------------- x -> bf16 convert (8 floats / thread) ----------------
__global__ void k_xconv(const float* __restrict__ x) {
    long long i = (long long)blockIdx.x * blockDim.x + threadIdx.x;
    const long long total = (long long)N_NODES * F_IN / 8;
    if (i >= total) return;
    float4 v0 = ((const float4*)x)[i * 2];
    float4 v1 = ((const float4*)x)[i * 2 + 1];
    uint4 o;
    o.x = pack_bf16x2(v0.x, v0.y);
    o.y = pack_bf16x2(v0.z, v0.w);
    o.z = pack_bf16x2(v1.x, v1.y);
    o.w = pack_bf16x2(v1.z, v1.w);
    ((uint4*)g_xb)[i] = o;
}

// ---------------- W preps (transpose to [N][K], bf16) ----------------
template <int Kd, int Nd>
__global__ void k_wprep(const float* __restrict__ W, uint16_t* __restrict__ Wt) {
    int i = blockIdx.x * blockDim.x + threadIdx.x;
    if (i >= Kd * Nd) return;
    int k = i / Nd, n = i % Nd;
    Wt[(size_t)n * Kd + k] = (uint16_t)(pack_bf16x2(W[i], 0.0f) & 0xffffu);
}

// ---------------- bf16 GEMM via mma.sync m16n8k16, cp.async x3 ------------
// Cb[M,Nd](bf16) = A[M,Kd](bf16) * Bt[Nd,Kd](bf16)^T.  BK=64 elements.
template <int Kd, int Nd>
__global__ void __launch_bounds__(512) k_gemm_bf16(const uint16_t* __restrict__ A,
                                                   const uint16_t* __restrict__ Bt,
                                                   uint16_t* __restrict__ Cb, int M) {
    constexpr int WN  = Nd / 8;
    constexpr int NT  = WN / 8;
    constexpr int STR = 36;                        // words per row (128B data + 16B pad)
    constexpr int ABYTES = 128 * STR * 4;
    constexpr int BBYTES = Nd * STR * 4;
    constexpr int KT = Kd / 64;
    extern __shared__ char smem[];
    const uint32_t sb = smem_u32(smem);

    const int t    = threadIdx.x;
    const int lane = t & 31, wid = t >> 5;
    const int gid  = lane >> 2, tig = lane & 3;
    const int wm   = (wid & 1) * 64;
    const int wn   = (wid >> 1) * WN;
    const int brow = blockIdx.x * 128;

    auto load_tile = [&](int kt, int buf) {
        uint32_t sA = sb + buf * ABYTES;
        uint32_t sB = sb + 3 * ABYTES + buf * BBYTES;
#pragma unroll
        for (int it = 0; it < 2; it++) {
            int f4 = it * 512 + t;
            int row = f4 >> 3, cq = f4 & 7;
            int grow = brow + row; if (grow > M - 1) grow = M - 1;
            cp16(sA + (uint32_t)(row * STR + cq * 4) * 4,
                 A + (size_t)grow * Kd + kt * 64 + cq * 8);
        }
#pragma unroll
        for (int it = 0; it < Nd / 64; it++) {
            int f4 = it * 512 + t;
            int n = f4 >> 3, cq = f4 & 7;
            cp16(sB + (uint32_t)(n * STR + cq * 4) * 4,
                 Bt + (size_t)n * Kd + kt * 64 + cq * 8);
        }
        cp_commit();
    };

    float c[4][NT][4];
#pragma unroll
    for (int mt = 0; mt < 4; mt++)
#pragma unroll
        for (int nt = 0; nt < NT; nt++)
#pragma unroll
            for (int i = 0; i < 4; i++) c[mt][nt][i] = 0.0f;

    load_tile(0, 0);
    load_tile(1, 1);
    for (int kt = 0; kt < KT; kt++) {
        int buf = kt % 3;
        if (kt + 2 < KT) { load_tile(kt + 2, (kt + 2) % 3); cp_wait<2>(); }
        else if (kt + 1 < KT) { cp_wait<1>(); }
        else { cp_wait<0>(); }
        __syncthreads();
        const uint32_t* As = (const uint32_t*)(smem + buf * ABYTES);
        const uint32_t* Bs = (const uint32_t*)(smem + 3 * ABYTES + buf * BBYTES);
#pragma unroll
        for (int ks = 0; ks < 4; ks++) {           // K=16 per step
            uint32_t a[4][4], b[NT][2];
#pragma unroll
            for (int mt = 0; mt < 4; mt++) {
                int r = wm + mt * 16;
                a[mt][0] = As[(r + gid)     * STR + ks * 8 + tig];
                a[mt][1] = As[(r + gid + 8) * STR + ks * 8 + tig];
                a[mt][2] = As[(r + gid)     * STR + ks * 8 + tig + 4];
                a[mt][3] = As[(r + gid + 8) * STR + ks * 8 + tig + 4];
            }
#pragma unroll
            for (int nt = 0; nt < NT; nt++) {
                int n = wn + nt * 8 + gid;
                b[nt][0] = Bs[n * STR + ks * 8 + tig];
                b[nt][1] = Bs[n * STR + ks * 8 + tig + 4];
            }
#pragma unroll
            for (int mt = 0; mt < 4; mt++)
#pragma unroll
                for (int nt = 0; nt < NT; nt++)
                    asm volatile(
                        "mma.sync.aligned.m16n8k16.row.col.f32.bf16.bf16.f32 "
                        "{%0,%1,%2,%3}, {%4,%5,%6,%7}, {%8,%9}, {%0,%1,%2,%3};"
                        : "+f"(c[mt][nt][0]), "+f"(c[mt][nt][1]),
                          "+f"(c[mt][nt][2]), "+f"(c[mt][nt][3])
                        : "r"(a[mt][0]), "r"(a[mt][1]), "r"(a[mt][2]), "r"(a[mt][3]),
                          "r"(b[nt][0]), "r"(b[nt][1]));
        }
        __syncthreads();
    }

#pragma unroll
    for (int mt = 0; mt < 4; mt++)
#pragma unroll
        for (int nt = 0; nt < NT; nt++) {
            int col = wn + nt * 8 + tig * 2;
            int r0  = brow + wm + mt * 16 + gid;
            int r1  = r0 + 8;
            if (r0 < M)
                *(uint32_t*)(Cb + (size_t)r0 * Nd + col) = pack_bf16x2(c[mt][nt][0], c[mt][nt][1]);
            if (r1 < M)
                *(uint32_t*)(Cb + (size_t)r1 * Nd + col) = pack_bf16x2(c[mt][nt][2], c[mt][nt][3]);
        }
}

// ---------------- threefry2x32 key (0,42) ----------------
__device__ __forceinline__ void threefry_0_42(unsigned c0, unsigned c1,
                                              unsigned& o0, unsigned& o1) {
    const unsigned ks0 = 0u, ks1 = 42u, ks2 = 0u ^ 42u ^ 0x1BD11BDAu;
    unsigned x0 = c0 + ks0, x1 = c1 + ks1;
#define TF_RND(r) { x0 += x1; x1 = __funnelshift_l(x1, x1, (r)); x1 ^= x0; }
    TF_RND(13) TF_RND(15) TF_RND(26) TF_RND(6)
    x0 += ks1; x1 += ks2 + 1u;
    TF_RND(17) TF_RND(29) TF_RND(16) TF_RND(24)
    x0 += ks2; x1 += ks0 + 2u;
    TF_RND(13) TF_RND(15) TF_RND(26) TF_RND(6)
    x0 += ks0; x1 += ks1 + 3u;
    TF_RND(17) TF_RND(29) TF_RND(16) TF_RND(24)
    x0 += ks1; x1 += ks2 + 4u;
    TF_RND(13) TF_RND(15) TF_RND(26) TF_RND(6)
    x0 += ks2; x1 += ks0 + 5u;
#undef TF_RND
    o0 = x0; o1 = x1;
}
__device__ __forceinline__ float tf_uniform(unsigned i) {
    unsigned r0, r1;
    threefry_0_42(0u, i, r0, r1);
    unsigned bits = r0 ^ r1;
    return __uint_as_float((bits >> 9) | 0x3f800000u) - 1.0f;
}

// ---------------- layer1 pull-agg -> bf16 agg1 ----------------------------
// 32 threads per node, 8 cols each; bf16 gathers, fp32 accum, bf16 output.
__global__ void __launch_bounds__(256) k_agg1(const float* __restrict__ b1) {
    int g    = threadIdx.x >> 5;
    int lane = threadIdx.x & 31;
    int node = blockIdx.x * 8 + g;
    if (node >= N_NODES) return;

    float dn = g_dinv[node];
    float s = dn * dn;
    uint4 rs = ((const uint4*)(g_h1b + (size_t)node * F_H))[lane];
    float acc[8] = {bf_lo(rs.x) * s, bf_hi(rs.x) * s, bf_lo(rs.y) * s, bf_hi(rs.y) * s,
                    bf_lo(rs.z) * s, bf_hi(rs.z) * s, bf_lo(rs.w) * s, bf_hi(rs.w) * s};

    int e0 = g_rowstart[node], e1 = g_rowstart[node + 1];
    int j = e0;
    for (; j + 2 <= e1; j += 2) {
        int s0 = g_csrc[j], s1 = g_csrc[j + 1];
        float n0 = dn * g_dinv[s0], n1 = dn * g_dinv[s1];
        uint4 r0 = ((const uint4*)(g_h1b + (size_t)s0 * F_H))[lane];
        uint4 r1 = ((const uint4*)(g_h1b + (size_t)s1 * F_H))[lane];
        acc[0] = fmaf(n0, bf_lo(r0.x), acc[0]); acc[1] = fmaf(n0, bf_hi(r0.x), acc[1]);
        acc[2] = fmaf(n0, bf_lo(r0.y), acc[2]); acc[3] = fmaf(n0, bf_hi(r0.y), acc[3]);
        acc[4] = fmaf(n0, bf_lo(r0.z), acc[4]); acc[5] = fmaf(n0, bf_hi(r0.z), acc[5]);
        acc[6] = fmaf(n0, bf_lo(r0.w), acc[6]); acc[7] = fmaf(n0, bf_hi(r0.w), acc[7]);
        acc[0] = fmaf(n1, bf_lo(r1.x), acc[0]); acc[1] = fmaf(n1, bf_hi(r1.x), acc[1]);
        acc[2] = fmaf(n1, bf_lo(r1.y), acc[2]); acc[3] = fmaf(n1, bf_hi(r1.y), acc[3]);
        acc[4] = fmaf(n1, bf_lo(r1.z), acc[4]); acc[5] = fmaf(n1, bf_hi(r1.z), acc[5]);
        acc[6] = fmaf(n1, bf_lo(r1.w), acc[6]); acc[7] = fmaf(n1, bf_hi(r1.w), acc[7]);
    }
    if (j < e1) {
        int s0 = g_csrc[j];
        float n0 = dn * g_dinv[s0];
        uint4 r0 = ((const uint4*)(g_h1b + (size_t)s0 * F_H))[lane];
        acc[0] = fmaf(n0, bf_lo(r0.x), acc[0]); acc[1] = fmaf(n0, bf_hi(r0.x), acc[1]);
        acc[2] = fmaf(n0, bf_lo(r0.y), acc[2]); acc[3] = fmaf(n0, bf_hi(r0.y), acc[3]);
        acc[4] = fmaf(n0, bf_lo(r0.z), acc[4]); acc[5] = fmaf(n0, bf_hi(r0.z), acc[5]);
        acc[6] = fmaf(n0, bf_lo(r0.w), acc[6]); acc[7] = fmaf(n0, bf_hi(r0.w), acc[7]);
    }
    const float4 bb0 = ((const float4*)b1)[lane * 2];
    const float4 bb1 = ((const float4*)b1)[lane * 2 + 1];
    float bias[8] = {bb0.x, bb0.y, bb0.z, bb0.w, bb1.x, bb1.y, bb1.z, bb1.w};
    unsigned i0 = (unsigned)node * F_H + lane * 8;
    float outv[8];
#pragma unroll
    for (int q = 0; q < 8; q++) {
        float v = fmaxf(acc[q] + bias[q], 0.0f);
        outv[q] = (tf_uniform(i0 + q) < 0.8f) ? v * 1.25f : 0.0f;
    }
    uint4 packed;
    packed.x = pack_bf16x2(outv[0], outv[1]);
    packed.y = pack_bf16x2(outv[2], outv[3]);
    packed.z = pack_bf16x2(outv[4], outv[5]);
    packed.w = pack_bf16x2(outv[6], outv[7]);
    ((uint4*)(g_agg1b + (size_t)node * F_H))[lane] = packed;
}

// ---------------- layer2 pull-agg + bias + softmax -> d_out ----------------
__global__ void __launch_bounds__(256) k_agg2(const float* __restrict__ b2,
                                              float* __restrict__ out) {
    int g    = threadIdx.x >> 5;
    int lane = threadIdx.x & 31;
    int node = blockIdx.x * 8 + g;
    if (node >= N_NODES) return;

    float dn = g_dinv[node];
    float s = dn * dn;
    uint2 rs = ((const uint2*)(g_h2b + (size_t)node * F_OUT))[lane];
    float4 acc = make_float4(bf_lo(rs.x) * s, bf_hi(rs.x) * s,
                             bf_lo(rs.y) * s, bf_hi(rs.y) * s);

    int e0 = g_rowstart[node], e1 = g_rowstart[node + 1];
    int j = e0;
    for (; j + 2 <= e1; j += 2) {
        int s0 = g_csrc[j], s1 = g_csrc[j + 1];
        float n0 = dn * g_dinv[s0], n1 = dn * g_dinv[s1];
        uint2 r0 = ((const uint2*)(g_h2b + (size_t)s0 * F_OUT))[lane];
        uint2 r1 = ((const uint2*)(g_h2b + (size_t)s1 * F_OUT))[lane];
        acc.x = fmaf(n0, bf_lo(r0.x), acc.x); acc.y = fmaf(n0, bf_hi(r0.x), acc.y);
        acc.z = fmaf(n0, bf_lo(r0.y), acc.z); acc.w = fmaf(n0, bf_hi(r0.y), acc.w);
        acc.x = fmaf(n1, bf_lo(r1.x), acc.x); acc.y = fmaf(n1, bf_hi(r1.x), acc.y);
        acc.z = fmaf(n1, bf_lo(r1.y), acc.z); acc.w = fmaf(n1, bf_hi(r1.y), acc.w);
    }
    if (j < e1) {
        int s0 = g_csrc[j];
        float n0 = dn * g_dinv[s0];
        uint2 r0 = ((const uint2*)(g_h2b + (size_t)s0 * F_OUT))[lane];
        acc.x = fmaf(n0, bf_lo(r0.x), acc.x); acc.y = fmaf(n0, bf_hi(r0.x), acc.y);
        acc.z = fmaf(n0, bf_lo(r0.y), acc.z); acc.w = fmaf(n0, bf_hi(r0.y), acc.w);
    }
    float4 bb = ((const float4*)b2)[lane];
    acc.x += bb.x; acc.y += bb.y; acc.z += bb.z; acc.w += bb.w;

    float m = fmaxf(fmaxf(acc.x, acc.y), fmaxf(acc.z, acc.w));
#pragma unroll
    for (int off = 16; off > 0; off >>= 1)
        m = fmaxf(m, __shfl_xor_sync(0xffffffffu, m, off));
    acc.x = expf(acc.x - m); acc.y = expf(acc.y - m);
    acc.z = expf(acc.z - m); acc.w = expf(acc.w - m);
    float sum = acc.x + acc.y + acc.z + acc.w;
#pragma unroll
    for (int off = 16; off > 0; off >>= 1)
        sum += __shfl_xor_sync(0xffffffffu, sum, off);
    float inv = 1.0f / sum;
    acc.x *= inv; acc.y *= inv; acc.z *= inv; acc.w *= inv;
    ((float4*)(out + (size_t)node * F_OUT))[lane] = acc;
}

// ---------------- launcher (fork-join) ----------
extern "C" void kernel_launch(void* const* d_in, const int* in_sizes, int n_in,
                              void* d_out, int out_size) {
    const float* x  = (const float*)d_in[0];
    const void*  ei = d_in[1];
    const float* W1 = (const float*)d_in[2];
    const float* b1 = (const float*)d_in[3];
    const float* W2 = (const float*)d_in[4];
    const float* b2 = (const float*)d_in[5];
    float* out = (float*)d_out;

    uint16_t* xb;    cudaGetSymbolAddress((void**)&xb,    g_xb);
    uint16_t* h1b;   cudaGetSymbolAddress((void**)&h1b,   g_h1b);
    uint16_t* agg1b; cudaGetSymbolAddress((void**)&agg1b, g_agg1b);
    uint16_t* h2b;   cudaGetSymbolAddress((void**)&h2b,   g_h2b);
    uint16_t* w1tb;  cudaGetSymbolAddress((void**)&w1tb,  g_w1tb);
    uint16_t* w2tb;  cudaGetSymbolAddress((void**)&w2tb,  g_w2tb);

    constexpr int STRB = 36 * 4;
    constexpr int SMEM1 = 3 * 128 * STRB + 3 * F_H  * STRB;  // 165888
    constexpr int SMEM2 = 3 * 128 * STRB + 3 * F_OUT * STRB; // 110592
    cudaFuncSetAttribute(k_gemm_bf16<F_IN, F_H>,
                         cudaFuncAttributeMaxDynamicSharedMemorySize, SMEM1);
    cudaFuncSetAttribute(k_gemm_bf16<F_H, F_OUT>,
                         cudaFuncAttributeMaxDynamicSharedMemorySize, SMEM2);

    const int MTILES = (N_NODES + 127) / 128;  // 391

    static cudaStream_t s_side = []() {
        cudaStream_t s; cudaStreamCreateWithFlags(&s, cudaStreamNonBlocking); return s;
    }();
    static cudaEvent_t ev_fork = []() {
        cudaEvent_t e; cudaEventCreateWithFlags(&e, cudaEventDisableTiming); return e;
    }();
    static cudaEvent_t ev_join = []() {
        cudaEvent_t e; cudaEventCreateWithFlags(&e, cudaEventDisableTiming); return e;
    }();

    // ---- fork ----
    cudaEventRecord(ev_fork, 0);
    cudaStreamWaitEvent(s_side, ev_fork, 0);

    // side chain: CSR build + W2 prep
    k_zero_detect<<<(N_NODES + 255) / 256, 256, 0, s_side>>>((const int*)ei);
    k_degree<<<(E_EDGES + 255) / 256, 256, 0, s_side>>>(ei);
    k_scan1<<<SCAN_NB, SCAN_B, 0, s_side>>>();
    k_scan2<<<1, 64, 0, s_side>>>();
    k_scan3<<<(N_NODES + 255) / 256, 256, 0, s_side>>>();
    k_fill<<<(E_EDGES + 255) / 256, 256, 0, s_side>>>(ei);
    k_wprep<F_H, F_OUT><<<(F_H * F_OUT + 255) / 256, 256, 0, s_side>>>(W2, w2tb);
    cudaEventRecord(ev_join, s_side);

    // main chain: x->bf16, W1 prep, bf16 GEMM1
    k_xconv<<<(int)(((long long)N_NODES * F_IN / 8 + 255) / 256), 256>>>(x);
    k_wprep<F_IN, F_H><<<(F_IN * F_H + 255) / 256, 256>>>(W1, w1tb);
    k_gemm_bf16<F_IN, F_H><<<MTILES, 512, SMEM1>>>(xb, w1tb, h1b, N_NODES);

    // ---- join ----
    cudaStreamWaitEvent(0, ev_join, 0);
    k_agg1<<<(N_NODES + 7) / 8, 256>>>(b1);
    k_gemm_bf16<F_H, F_OUT><<<MTILES, 512, SMEM2>>>(agg1b, w2tb, h2b, N_NODES);
    k_agg2<<<(N_NODES + 7) / 8, 256>>>(b2, out);
}

// round 17
// speedup vs baseline: 1.3298x; 1.0554x over previous
#include <cuda_runtime.h>
#include <cstdint>

// ---------------- problem constants ----------------
#define N_NODES 50000
#define F_IN    512
#define F_H     256
#define F_OUT   128
#define E_EDGES 800000
#define SCAN_B  1024
#define SCAN_NB ((N_NODES + SCAN_B - 1) / SCAN_B)   // 49

// ---------------- scratch (static device globals; no runtime alloc) --------
__device__ int   g_is64;
__device__ int   g_deg [N_NODES];
__device__ int   g_cursor[N_NODES];
__device__ int   g_rowstart[N_NODES + 1];
__device__ int   g_bsum[SCAN_NB];
__device__ int   g_csrc[E_EDGES];
__device__ float g_dinv[N_NODES];
__device__ uint16_t g_h1b  [(size_t)N_NODES * F_H];   // bf16 h1
__device__ uint16_t g_agg1b[(size_t)N_NODES * F_H];   // bf16 agg1
__device__ uint16_t g_h2b  [(size_t)N_NODES * F_OUT]; // bf16 h2
__device__ uint16_t g_w1tb[F_IN * F_H];               // W1^T bf16 [N][K]
__device__ uint16_t g_w2tb[F_H * F_OUT];              // W2^T bf16 [N][K]

// ---------------- helpers ----------------
__device__ __forceinline__ uint32_t pack_bf16x2(float lo, float hi) {
    uint32_t r; asm("cvt.rn.bf16x2.f32 %0, %1, %2;" : "=r"(r) : "f"(hi), "f"(lo)); return r;
}
__device__ __forceinline__ float bf_lo(uint32_t u) { return __uint_as_float(u << 16); }
__device__ __forceinline__ float bf_hi(uint32_t u) { return __uint_as_float(u & 0xffff0000u); }
__device__ __forceinline__ uint32_t smem_u32(const void* p) {
    uint32_t a;
    asm("{ .reg .u64 t; cvta.to.shared.u64 t, %1; cvt.u32.u64 %0, t; }" : "=r"(a) : "l"(p));
    return a;
}
__device__ __forceinline__ void cp16(uint32_t s, const void* g) {
    asm volatile("cp.async.cg.shared.global [%0], [%1], 16;" :: "r"(s), "l"(g));
}
__device__ __forceinline__ void cp_commit() {
    asm volatile("cp.async.commit_group;" ::: "memory");
}
template <int N>
__device__ __forceinline__ void cp_wait() {
    asm volatile("cp.async.wait_group %0;" :: "n"(N) : "memory");
}

// ---------------- edge index access (int32 or int64) ----------------
__device__ __forceinline__ int edge_at(const void* ei, long long i) {
    if (g_is64) return (int)((const long long*)ei)[i];
    return ((const int*)ei)[i];
}

// ---------------- zero + dtype detect (fused) ----------------
__global__ void k_zero_detect(const int* ei32) {
    int i = blockIdx.x * blockDim.x + threadIdx.x;
    if (i < N_NODES) g_deg[i] = 0;
    if (blockIdx.x == 0) {
        __shared__ int nz[256];
        int acc = 0;
#pragma unroll
        for (int u = 0; u < 8; u++)
            acc |= ei32[2 * (threadIdx.x * 8 + u) + 1];
        nz[threadIdx.x] = acc;
        __syncthreads();
        for (int off = 128; off > 0; off >>= 1) {
            if (threadIdx.x < off) nz[threadIdx.x] |= nz[threadIdx.x + off];
            __syncthreads();
        }
        if (threadIdx.x == 0) g_is64 = (nz[0] == 0) ? 1 : 0;
    }
}
__global__ void k_degree(const void* ei) {
    int e = blockIdx.x * blockDim.x + threadIdx.x;
    if (e < E_EDGES) atomicAdd(&g_deg[edge_at(ei, (long long)E_EDGES + e)], 1);
}
__global__ void __launch_bounds__(SCAN_B) k_scan1() {
    __shared__ int ws[32];
    int i = blockIdx.x * SCAN_B + threadIdx.x;
    int lane = threadIdx.x & 31, warp = threadIdx.x >> 5;
    int v = (i < N_NODES) ? g_deg[i] : 0;
    if (i < N_NODES) g_dinv[i] = rsqrtf((float)(v + 1));
    int inc = v;
#pragma unroll
    for (int off = 1; off < 32; off <<= 1) {
        int y = __shfl_up_sync(0xffffffffu, inc, off);
        if (lane >= off) inc += y;
    }
    if (lane == 31) ws[warp] = inc;
    __syncthreads();
    if (warp == 0) {
        int s = ws[lane];
        int sinc = s;
#pragma unroll
        for (int off = 1; off < 32; off <<= 1) {
            int y = __shfl_up_sync(0xffffffffu, sinc, off);
            if (lane >= off) sinc += y;
        }
        ws[lane] = sinc - s;
        if (lane == 31) g_bsum[blockIdx.x] = sinc;
    }
    __syncthreads();
    if (i < N_NODES) g_rowstart[i] = ws[warp] + inc - v;
}
__global__ void k_scan2() {
    __shared__ int s[SCAN_NB];
    if (threadIdx.x < SCAN_NB) s[threadIdx.x] = g_bsum[threadIdx.x];
    __syncthreads();
    if (threadIdx.x == 0) {
        int run = 0;
        for (int b = 0; b < SCAN_NB; b++) { int t = s[b]; s[b] = run; run += t; }
    }
    __syncthreads();
    if (threadIdx.x < SCAN_NB) g_bsum[threadIdx.x] = s[threadIdx.x];
}
__global__ void k_scan3() {
    int i = blockIdx.x * blockDim.x + threadIdx.x;
    if (i < N_NODES) {
        int rs = g_rowstart[i] + g_bsum[i >> 10];
        g_rowstart[i] = rs;
        g_cursor[i]   = rs;
    }
    if (i == 0) g_rowstart[N_NODES] = E_EDGES;
}
__global__ void k_fill(const void* ei) {
    int e = blockIdx.x * blockDim.x + threadIdx.x;
    if (e >= E_EDGES) return;
    int src = edge_at(ei, e);
    int dst = edge_at(ei, (long long)E_EDGES + e);
    int pos = atomicAdd(&g_cursor[dst], 1);
    g_csrc[pos] = src;
}

// ---------------- W preps (transpose to [N][K], bf16) ----------------
template <int Kd, int Nd>
__global__ void k_wprep(const float* __restrict__ W, uint16_t* __restrict__ Wt) {
    int i = blockIdx.x * blockDim.x + threadIdx.x;
    if (i >= Kd * Nd) return;
    int k = i / Nd, n = i % Nd;
    Wt[(size_t)n * Kd + k] = (uint16_t)(pack_bf16x2(W[i], 0.0f) & 0xffffu);
}

// ---------------- GEMM1: fp32 A fused-convert + bf16 mma, cp.async B x3 ----
// Cb[M,Nd](bf16) = bf16(A[M,Kd] fp32) * Bt[Nd,Kd](bf16)^T.  BK=64.
// A: register-prefetch double buffer (LDG fp32 -> cvt -> STS), single smem buf.
template <int Kd, int Nd>
__global__ void __launch_bounds__(512) k_gemm1_fused(const float* __restrict__ A,
                                                     const uint16_t* __restrict__ Bt,
                                                     uint16_t* __restrict__ Cb, int M) {
    constexpr int WN  = Nd / 8;
    constexpr int NT  = WN / 8;
    constexpr int STR = 36;                        // words per 128B row (+16B pad)
    constexpr int ABYTES = 128 * STR * 4;          // single buffer
    constexpr int BBYTES = Nd * STR * 4;
    constexpr int KT = Kd / 64;
    extern __shared__ char smem[];
    const uint32_t sb = smem_u32(smem);

    const int t    = threadIdx.x;
    const int lane = t & 31, wid = t >> 5;
    const int gid  = lane >> 2, tig = lane & 3;
    const int wm   = (wid & 1) * 64;
    const int wn   = (wid >> 1) * WN;
    const int brow = blockIdx.x * 128;

    // per-thread A chunk coords (2 chunks of 8 bf16)
    int rowc[2], cqc[2];
#pragma unroll
    for (int it = 0; it < 2; it++) {
        int f4 = it * 512 + t;
        rowc[it] = f4 >> 3;
        cqc[it]  = f4 & 7;
    }

    auto ldgA = [&](int kt, uint4* pk) {
#pragma unroll
        for (int it = 0; it < 2; it++) {
            int grow = brow + rowc[it]; if (grow > M - 1) grow = M - 1;
            const float4* p = (const float4*)(A + (size_t)grow * Kd + kt * 64 + cqc[it] * 8);
            float4 v0 = p[0], v1 = p[1];
            pk[it].x = pack_bf16x2(v0.x, v0.y);
            pk[it].y = pack_bf16x2(v0.z, v0.w);
            pk[it].z = pack_bf16x2(v1.x, v1.y);
            pk[it].w = pack_bf16x2(v1.z, v1.w);
        }
    };
    auto stsA = [&](const uint4* pk) {
#pragma unroll
        for (int it = 0; it < 2; it++)
            *(uint4*)(smem + (uint32_t)(rowc[it] * STR + cqc[it] * 4) * 4) = pk[it];
    };
    auto cpB = [&](int kt, int buf) {
        uint32_t sB = sb + ABYTES + buf * BBYTES;
#pragma unroll
        for (int it = 0; it < Nd / 64; it++) {
            int f4 = it * 512 + t;
            int n = f4 >> 3, cq = f4 & 7;
            cp16(sB + (uint32_t)(n * STR + cq * 4) * 4,
                 Bt + (size_t)n * Kd + kt * 64 + cq * 8);
        }
        cp_commit();
    };

    float c[4][NT][4];
#pragma unroll
    for (int mt = 0; mt < 4; mt++)
#pragma unroll
        for (int nt = 0; nt < NT; nt++)
#pragma unroll
            for (int i = 0; i < 4; i++) c[mt][nt][i] = 0.0f;

    uint4 pk[2];
    ldgA(0, pk);
    cpB(0, 0);
    cpB(1, 1);
    for (int kt = 0; kt < KT; kt++) {
        int buf = kt % 3;
        stsA(pk);
        if (kt + 1 < KT) ldgA(kt + 1, pk);     // prefetch next A (latency under compute)
        if (kt + 2 < KT) { cpB(kt + 2, (kt + 2) % 3); cp_wait<2>(); }
        else if (kt + 1 < KT) { cp_wait<1>(); }
        else { cp_wait<0>(); }
        __syncthreads();
        const uint32_t* As = (const uint32_t*)smem;
        const uint32_t* Bs = (const uint32_t*)(smem + ABYTES + buf * BBYTES);
#pragma unroll
        for (int ks = 0; ks < 4; ks++) {
            uint32_t a[4][4], b[NT][2];
#pragma unroll
            for (int mt = 0; mt < 4; mt++) {
                int r = wm + mt * 16;
                a[mt][0] = As[(r + gid)     * STR + ks * 8 + tig];
                a[mt][1] = As[(r + gid + 8) * STR + ks * 8 + tig];
                a[mt][2] = As[(r + gid)     * STR + ks * 8 + tig + 4];
                a[mt][3] = As[(r + gid + 8) * STR + ks * 8 + tig + 4];
            }
#pragma unroll
            for (int nt = 0; nt < NT; nt++) {
                int n = wn + nt * 8 + gid;
                b[nt][0] = Bs[n * STR + ks * 8 + tig];
                b[nt][1] = Bs[n * STR + ks * 8 + tig + 4];
            }
#pragma unroll
            for (int mt = 0; mt < 4; mt++)
#pragma unroll
                for (int nt = 0; nt < NT; nt++)
                    asm volatile(
                        "mma.sync.aligned.m16n8k16.row.col.f32.bf16.bf16.f32 "
                        "{%0,%1,%2,%3}, {%4,%5,%6,%7}, {%8,%9}, {%0,%1,%2,%3};"
                        : "+f"(c[mt][nt][0]), "+f"(c[mt][nt][1]),
                          "+f"(c[mt][nt][2]), "+f"(c[mt][nt][3])
                        : "r"(a[mt][0]), "r"(a[mt][1]), "r"(a[mt][2]), "r"(a[mt][3]),
                          "r"(b[nt][0]), "r"(b[nt][1]));
        }
        __syncthreads();
    }

#pragma unroll
    for (int mt = 0; mt < 4; mt++)
#pragma unroll
        for (int nt = 0; nt < NT; nt++) {
            int col = wn + nt * 8 + tig * 2;
            int r0  = brow + wm + mt * 16 + gid;
            int r1  = r0 + 8;
            if (r0 < M)
                *(uint32_t*)(Cb + (size_t)r0 * Nd + col) = pack_bf16x2(c[mt][nt][0], c[mt][nt][1]);
            if (r1 < M)
                *(uint32_t*)(Cb + (size_t)r1 * Nd + col) = pack_bf16x2(c[mt][nt][2], c[mt][nt][3]);
        }
}

// ---------------- bf16 GEMM (A bf16), cp.async x3 — layer 2 ---------------
template <int Kd, int Nd>
__global__ void __launch_bounds__(512) k_gemm_bf16(const uint16_t* __restrict__ A,
                                                   const uint16_t* __restrict__ Bt,
                                                   uint16_t* __restrict__ Cb, int M) {
    constexpr int WN  = Nd / 8;
    constexpr int NT  = WN / 8;
    constexpr int STR = 36;
    constexpr int ABYTES = 128 * STR * 4;
    constexpr int BBYTES = Nd * STR * 4;
    constexpr int KT = Kd / 64;
    extern __shared__ char smem[];
    const uint32_t sb = smem_u32(smem);

    const int t    = threadIdx.x;
    const int lane = t & 31, wid = t >> 5;
    const int gid  = lane >> 2, tig = lane & 3;
    const int wm   = (wid & 1) * 64;
    const int wn   = (wid >> 1) * WN;
    const int brow = blockIdx.x * 128;

    auto load_tile = [&](int kt, int buf) {
        uint32_t sA = sb + buf * ABYTES;
        uint32_t sB = sb + 3 * ABYTES + buf * BBYTES;
#pragma unroll
        for (int it = 0; it < 2; it++) {
            int f4 = it * 512 + t;
            int row = f4 >> 3, cq = f4 & 7;
            int grow = brow + row; if (grow > M - 1) grow = M - 1;
            cp16(sA + (uint32_t)(row * STR + cq * 4) * 4,
                 A + (size_t)grow * Kd + kt * 64 + cq * 8);
        }
#pragma unroll
        for (int it = 0; it < Nd / 64; it++) {
            int f4 = it * 512 + t;
            int n = f4 >> 3, cq = f4 & 7;
            cp16(sB + (uint32_t)(n * STR + cq * 4) * 4,
                 Bt + (size_t)n * Kd + kt * 64 + cq * 8);
        }
        cp_commit();
    };

    float c[4][NT][4];
#pragma unroll
    for (int mt = 0; mt < 4; mt++)
#pragma unroll
        for (int nt = 0; nt < NT; nt++)
#pragma unroll
            for (int i = 0; i < 4; i++) c[mt][nt][i] = 0.0f;

    load_tile(0, 0);
    load_tile(1, 1);
    for (int kt = 0; kt < KT; kt++) {
        int buf = kt % 3;
        if (kt + 2 < KT) { load_tile(kt + 2, (kt + 2) % 3); cp_wait<2>(); }
        else if (kt + 1 < KT) { cp_wait<1>(); }
        else { cp_wait<0>(); }
        __syncthreads();
        const uint32_t* As = (const uint32_t*)(smem + buf * ABYTES);
        const uint32_t* Bs = (const uint32_t*)(smem + 3 * ABYTES + buf * BBYTES);
#pragma unroll
        for (int ks = 0; ks < 4; ks++) {
            uint32_t a[4][4], b[NT][2];
#pragma unroll
            for (int mt = 0; mt < 4; mt++) {
                int r = wm + mt * 16;
                a[mt][0] = As[(r + gid)     * STR + ks * 8 + tig];
                a[mt][1] = As[(r + gid + 8) * STR + ks * 8 + tig];
                a[mt][2] = As[(r + gid)     * STR + ks * 8 + tig + 4];
                a[mt][3] = As[(r + gid + 8) * STR + ks * 8 + tig + 4];
            }
#pragma unroll
            for (int nt = 0; nt < NT; nt++) {
                int n = wn + nt * 8 + gid;
                b[nt][0] = Bs[n * STR + ks * 8 + tig];
                b[nt][1] = Bs[n * STR + ks * 8 + tig + 4];
            }
#pragma unroll
            for (int mt = 0; mt < 4; mt++)
#pragma unroll
                for (int nt = 0; nt < NT; nt++)
                    asm volatile(
                        "mma.sync.aligned.m16n8k16.row.col.f32.bf16.bf16.f32 "
                        "{%0,%1,%2,%3}, {%4,%5,%6,%7}, {%8,%9}, {%0,%1,%2,%3};"
                        : "+f"(c[mt][nt][0]), "+f"(c[mt][nt][1]),
                          "+f"(c[mt][nt][2]), "+f"(c[mt][nt][3])
                        : "r"(a[mt][0]), "r"(a[mt][1]), "r"(a[mt][2]), "r"(a[mt][3]),
                          "r"(b[nt][0]), "r"(b[nt][1]));
        }
        __syncthreads();
    }

#pragma unroll
    for (int mt = 0; mt < 4; mt++)
#pragma unroll
        for (int nt = 0; nt < NT; nt++) {
            int col = wn + nt * 8 + tig * 2;
            int r0  = brow + wm + mt * 16 + gid;
            int r1  = r0 + 8;
            if (r0 < M)
                *(uint32_t*)(Cb + (size_t)r0 * Nd + col) = pack_bf16x2(c[mt][nt][0], c[mt][nt][1]);
            if (r1 < M)
                *(uint32_t*)(Cb + (size_t)r1 * Nd + col) = pack_bf16x2(c[mt][nt][2], c[mt][nt][3]);
        }
}

// ---------------- threefry2x32 key (0,42) ----------------
__device__ __forceinline__ void threefry_0_42(unsigned c0, unsigned c1,
                                              unsigned& o0, unsigned& o1) {
    const unsigned ks0 = 0u, ks1 = 42u, ks2 = 0u ^ 42u ^ 0x1BD11BDAu;
    unsigned x0 = c0 + ks0, x1 = c1 + ks1;
#define TF_RND(r) { x0 += x1; x1 = __funnelshift_l(x1, x1, (r)); x1 ^= x0; }
    TF_RND(13) TF_RND(15) TF_RND(26) TF_RND(6)
    x0 += ks1; x1 += ks2 + 1u;
    TF_RND(17) TF_RND(29) TF_RND(16) TF_RND(24)
    x0 += ks2; x1 += ks0 + 2u;
    TF_RND(13) TF_RND(15) TF_RND(26) TF_RND(6)
    x0 += ks0; x1 += ks1 + 3u;
    TF_RND(17) TF_RND(29) TF_RND(16) TF_RND(24)
    x0 += ks1; x1 += ks2 + 4u;
    TF_RND(13) TF_RND(15) TF_RND(26) TF_RND(6)
    x0 += ks2; x1 += ks0 + 5u;
#undef TF_RND
    o0 = x0; o1 = x1;
}
__device__ __forceinline__ float tf_uniform(unsigned i) {
    unsigned r0, r1;
    threefry_0_42(0u, i, r0, r1);
    unsigned bits = r0 ^ r1;
    return __uint_as_float((bits >> 9) | 0x3f800000u) - 1.0f;
}

// ---------------- layer1 pull-agg -> bf16 agg1 ----------------------------
__global__ void __launch_bounds__(256) k_agg1(const float* __restrict__ b1) {
    int g    = threadIdx.x >> 5;
    int lane = threadIdx.x & 31;
    int node = blockIdx.x * 8 + g;
    if (node >= N_NODES) return;

    float dn = g_dinv[node];
    float s = dn * dn;
    uint4 rs = ((const uint4*)(g_h1b + (size_t)node * F_H))[lane];
    float acc[8] = {bf_lo(rs.x) * s, bf_hi(rs.x) * s, bf_lo(rs.y) * s, bf_hi(rs.y) * s,
                    bf_lo(rs.z) * s, bf_hi(rs.z) * s, bf_lo(rs.w) * s, bf_hi(rs.w) * s};

    int e0 = g_rowstart[node], e1 = g_rowstart[node + 1];
    int j = e0;
    for (; j + 2 <= e1; j += 2) {
        int s0 = g_csrc[j], s1 = g_csrc[j + 1];
        float n0 = dn * g_dinv[s0], n1 = dn * g_dinv[s1];
        uint4 r0 = ((const uint4*)(g_h1b + (size_t)s0 * F_H))[lane];
        uint4 r1 = ((const uint4*)(g_h1b + (size_t)s1 * F_H))[lane];
        acc[0] = fmaf(n0, bf_lo(r0.x), acc[0]); acc[1] = fmaf(n0, bf_hi(r0.x), acc[1]);
        acc[2] = fmaf(n0, bf_lo(r0.y), acc[2]); acc[3] = fmaf(n0, bf_hi(r0.y), acc[3]);
        acc[4] = fmaf(n0, bf_lo(r0.z), acc[4]); acc[5] = fmaf(n0, bf_hi(r0.z), acc[5]);
        acc[6] = fmaf(n0, bf_lo(r0.w), acc[6]); acc[7] = fmaf(n0, bf_hi(r0.w), acc[7]);
        acc[0] = fmaf(n1, bf_lo(r1.x), acc[0]); acc[1] = fmaf(n1, bf_hi(r1.x), acc[1]);
        acc[2] = fmaf(n1, bf_lo(r1.y), acc[2]); acc[3] = fmaf(n1, bf_hi(r1.y), acc[3]);
        acc[4] = fmaf(n1, bf_lo(r1.z), acc[4]); acc[5] = fmaf(n1, bf_hi(r1.z), acc[5]);
        acc[6] = fmaf(n1, bf_lo(r1.w), acc[6]); acc[7] = fmaf(n1, bf_hi(r1.w), acc[7]);
    }
    if (j < e1) {
        int s0 = g_csrc[j];
        float n0 = dn * g_dinv[s0];
        uint4 r0 = ((const uint4*)(g_h1b + (size_t)s0 * F_H))[lane];
        acc[0] = fmaf(n0, bf_lo(r0.x), acc[0]); acc[1] = fmaf(n0, bf_hi(r0.x), acc[1]);
        acc[2] = fmaf(n0, bf_lo(r0.y), acc[2]); acc[3] = fmaf(n0, bf_hi(r0.y), acc[3]);
        acc[4] = fmaf(n0, bf_lo(r0.z), acc[4]); acc[5] = fmaf(n0, bf_hi(r0.z), acc[5]);
        acc[6] = fmaf(n0, bf_lo(r0.w), acc[6]); acc[7] = fmaf(n0, bf_hi(r0.w), acc[7]);
    }
    const float4 bb0 = ((const float4*)b1)[lane * 2];
    const float4 bb1 = ((const float4*)b1)[lane * 2 + 1];
    float bias[8] = {bb0.x, bb0.y, bb0.z, bb0.w, bb1.x, bb1.y, bb1.z, bb1.w};
    unsigned i0 = (unsigned)node * F_H + lane * 8;
    float outv[8];
#pragma unroll
    for (int q = 0; q < 8; q++) {
        float v = fmaxf(acc[q] + bias[q], 0.0f);
        outv[q] = (tf_uniform(i0 + q) < 0.8f) ? v * 1.25f : 0.0f;
    }
    uint4 packed;
    packed.x = pack_bf16x2(outv[0], outv[1]);
    packed.y = pack_bf16x2(outv[2], outv[3]);
    packed.z = pack_bf16x2(outv[4], outv[5]);
    packed.w = pack_bf16x2(outv[6], outv[7]);
    ((uint4*)(g_agg1b + (size_t)node * F_H))[lane] = packed;
}

// ---------------- layer2 pull-agg + bias + softmax -> d_out ----------------
__global__ void __launch_bounds__(256) k_agg2(const float* __restrict__ b2,
                                              float* __restrict__ out) {
    int g    = threadIdx.x >> 5;
    int lane = threadIdx.x & 31;
    int node = blockIdx.x * 8 + g;
    if (node >= N_NODES) return;

    float dn = g_dinv[node];
    float s = dn * dn;
    uint2 rs = ((const uint2*)(g_h2b + (size_t)node * F_OUT))[lane];
    float4 acc = make_float4(bf_lo(rs.x) * s, bf_hi(rs.x) * s,
                             bf_lo(rs.y) * s, bf_hi(rs.y) * s);

    int e0 = g_rowstart[node], e1 = g_rowstart[node + 1];
    int j = e0;
    for (; j + 2 <= e1; j += 2) {
        int s0 = g_csrc[j], s1 = g_csrc[j + 1];
        float n0 = dn * g_dinv[s0], n1 = dn * g_dinv[s1];
        uint2 r0 = ((const uint2*)(g_h2b + (size_t)s0 * F_OUT))[lane];
        uint2 r1 = ((const uint2*)(g_h2b + (size_t)s1 * F_OUT))[lane];
        acc.x = fmaf(n0, bf_lo(r0.x), acc.x); acc.y = fmaf(n0, bf_hi(r0.x), acc.y);
        acc.z = fmaf(n0, bf_lo(r0.y), acc.z); acc.w = fmaf(n0, bf_hi(r0.y), acc.w);
        acc.x = fmaf(n1, bf_lo(r1.x), acc.x); acc.y = fmaf(n1, bf_hi(r1.x), acc.y);
        acc.z = fmaf(n1, bf_lo(r1.y), acc.z); acc.w = fmaf(n1, bf_hi(r1.y), acc.w);
    }
    if (j < e1) {
        int s0 = g_csrc[j];
        float n0 = dn * g_dinv[s0];
        uint2 r0 = ((const uint2*)(g_h2b + (size_t)s0 * F_OUT))[lane];
        acc.x = fmaf(n0, bf_lo(r0.x), acc.x); acc.y = fmaf(n0, bf_hi(r0.x), acc.y);
        acc.z = fmaf(n0, bf_lo(r0.y), acc.z); acc.w = fmaf(n0, bf_hi(r0.y), acc.w);
    }
    float4 bb = ((const float4*)b2)[lane];
    acc.x += bb.x; acc.y += bb.y; acc.z += bb.z; acc.w += bb.w;

    float m = fmaxf(fmaxf(acc.x, acc.y), fmaxf(acc.z, acc.w));
#pragma unroll
    for (int off = 16; off > 0; off >>= 1)
        m = fmaxf(m, __shfl_xor_sync(0xffffffffu, m, off));
    acc.x = expf(acc.x - m); acc.y = expf(acc.y - m);
    acc.z = expf(acc.z - m); acc.w = expf(acc.w - m);
    float sum = acc.x + acc.y + acc.z + acc.w;
#pragma unroll
    for (int off = 16; off > 0; off >>= 1)
        sum += __shfl_xor_sync(0xffffffffu, sum, off);
    float inv = 1.0f / sum;
    acc.x *= inv; acc.y *= inv; acc.z *= inv; acc.w *= inv;
    ((float4*)(out + (size_t)node * F_OUT))[lane] = acc;
}

// ---------------- launcher (fork-join; wprep1 at side head) ----------
extern "C" void kernel_launch(void* const* d_in, const int* in_sizes, int n_in,
                              void* d_out, int out_size) {
    const float* x  = (const float*)d_in[0];
    const void*  ei = d_in[1];
    const float* W1 = (const float*)d_in[2];
    const float* b1 = (const float*)d_in[3];
    const float* W2 = (const float*)d_in[4];
    const float* b2 = (const float*)d_in[5];
    float* out = (float*)d_out;

    uint16_t* h1b;   cudaGetSymbolAddress((void**)&h1b,   g_h1b);
    uint16_t* agg1b; cudaGetSymbolAddress((void**)&agg1b, g_agg1b);
    uint16_t* h2b;   cudaGetSymbolAddress((void**)&h2b,   g_h2b);
    uint16_t* w1tb;  cudaGetSymbolAddress((void**)&w1tb,  g_w1tb);
    uint16_t* w2tb;  cudaGetSymbolAddress((void**)&w2tb,  g_w2tb);

    constexpr int STRB = 36 * 4;
    constexpr int SMEM1 = 1 * 128 * STRB + 3 * F_H  * STRB;  // 129024
    constexpr int SMEM2 = 3 * 128 * STRB + 3 * F_OUT * STRB; // 110592
    cudaFuncSetAttribute(k_gemm1_fused<F_IN, F_H>,
                         cudaFuncAttributeMaxDynamicSharedMemorySize, SMEM1);
    cudaFuncSetAttribute(k_gemm_bf16<F_H, F_OUT>,
                         cudaFuncAttributeMaxDynamicSharedMemorySize, SMEM2);

    const int MTILES = (N_NODES + 127) / 128;  // 391

    static cudaStream_t s_side = []() {
        cudaStream_t s; cudaStreamCreateWithFlags(&s, cudaStreamNonBlocking); return s;
    }();
    static cudaEvent_t ev_fork = []() {
        cudaEvent_t e; cudaEventCreateWithFlags(&e, cudaEventDisableTiming); return e;
    }();
    static cudaEvent_t ev_w1 = []() {
        cudaEvent_t e; cudaEventCreateWithFlags(&e, cudaEventDisableTiming); return e;
    }();
    static cudaEvent_t ev_join = []() {
        cudaEvent_t e; cudaEventCreateWithFlags(&e, cudaEventDisableTiming); return e;
    }();

    // ---- fork ----
    cudaEventRecord(ev_fork, 0);
    cudaStreamWaitEvent(s_side, ev_fork, 0);

    // side chain: W1 prep (needed first by main), CSR build, W2 prep
    k_wprep<F_IN, F_H><<<(F_IN * F_H + 255) / 256, 256, 0, s_side>>>(W1, w1tb);
    cudaEventRecord(ev_w1, s_side);
    k_zero_detect<<<(N_NODES + 255) / 256, 256, 0, s_side>>>((const int*)ei);
    k_degree<<<(E_EDGES + 255) / 256, 256, 0, s_side>>>(ei);
    k_scan1<<<SCAN_NB, SCAN_B, 0, s_side>>>();
    k_scan2<<<1, 64, 0, s_side>>>();
    k_scan3<<<(N_NODES + 255) / 256, 256, 0, s_side>>>();
    k_fill<<<(E_EDGES + 255) / 256, 256, 0, s_side>>>(ei);
    k_wprep<F_H, F_OUT><<<(F_H * F_OUT + 255) / 256, 256, 0, s_side>>>(W2, w2tb);
    cudaEventRecord(ev_join, s_side);

    // main chain: GEMM1 (fused fp32->bf16 A load)
    cudaStreamWaitEvent(0, ev_w1, 0);
    k_gemm1_fused<F_IN, F_H><<<MTILES, 512, SMEM1>>>(x, w1tb, h1b, N_NODES);

    // ---- join ----
    cudaStreamWaitEvent(0, ev_join, 0);
    k_agg1<<<(N_NODES + 7) / 8, 256>>>(b1);
    k_gemm_bf16<F_H, F_OUT><<<MTILES, 512, SMEM2>>>(agg1b, w2tb, h2b, N_NODES);
    k_agg2<<<(N_NODES + 7) / 8, 256>>>(b2, out);
}